// round 12
// baseline (speedup 1.0000x reference)
#include <cuda_runtime.h>
#include <cstdint>

#define BB_  4
#define NN_  2048
#define CC_  512
#define HH_  8
#define HD_  64
// q pre-scale: (1/sqrt(64)) * log2(e)  -> scores arrive in log2 domain
#define QSCALE_ 0.18033688011112042f

// d_out layout: [ out (B*N*C) | k (B*H*N*hd) | v (B*H*N*hd) ]
#define KOFF_ (4u * 2048u * 512u)
#define VOFF_ (8u * 2048u * 512u)

// scratch
__device__ float g_q  [BB_ * HH_ * NN_ * HD_];   // pre-scaled q (log2 domain)
__device__ float g_ao [BB_ * NN_ * CC_];         // attention out [B,N,C]
__device__ float g_wt [1536 * 512];              // W_qkv^T  [N][K], tf32-rounded
__device__ float g_wtp[512 * 512];               // W_proj^T [N][K], tf32-rounded

// ===========================================================================
// m16n8k8 tf32 mma (base ISA, works on plain sm_103 target)
// ===========================================================================
__device__ __forceinline__ void mma_tf32(float (&d)[4], const uint32_t (&a)[4],
                                         const uint32_t (&b)[2]) {
    asm volatile(
        "mma.sync.aligned.m16n8k8.row.col.f32.tf32.tf32.f32 "
        "{%0,%1,%2,%3}, {%4,%5,%6,%7}, {%8,%9}, {%0,%1,%2,%3};"
        : "+f"(d[0]), "+f"(d[1]), "+f"(d[2]), "+f"(d[3])
        : "r"(a[0]), "r"(a[1]), "r"(a[2]), "r"(a[3]), "r"(b[0]), "r"(b[1]));
}

__device__ __forceinline__ uint32_t tf32_rna(float x) {
    uint32_t r;
    asm("cvt.rna.tf32.f32 %0, %1;" : "=r"(r) : "f"(x));
    return r;
}
__device__ __forceinline__ float rnaf(float x) {
    return __uint_as_float(tf32_rna(x));
}
__device__ __forceinline__ float4 rna4(float4 v) {
    v.x = rnaf(v.x); v.y = rnaf(v.y); v.z = rnaf(v.z); v.w = rnaf(v.w);
    return v;
}

// fast 2^t on fma/alu pipes only (no MUFU). t >= -100 clamped; |err| ~ 3e-6.
__device__ __forceinline__ float fexp2(float t) {
    t = fmaxf(t, -100.f);
    float z = t + 12582912.f;
    int   n = __float_as_int(z) - 0x4B400000;
    float f = t - (z - 12582912.f);
    float p =        1.3333558e-3f;
    p = fmaf(p, f, 9.6181291e-3f);
    p = fmaf(p, f, 5.5504109e-2f);
    p = fmaf(p, f, 2.4022651e-1f);
    p = fmaf(p, f, 6.9314718e-1f);
    p = fmaf(p, f, 1.0f);
    return __int_as_float(__float_as_int(p) + (n << 23));
}

// ===========================================================================
// W transpose + tf32 pre-round: src[R][C] -> dst[C][R] (dst in device code)
// which: 0 -> g_wt, 1 -> g_wtp
// ===========================================================================
__global__ void transpose_kernel(const float* __restrict__ src,
                                 int which, int R, int C)
{
    float* dst = which ? g_wtp : g_wt;
    __shared__ float tile[32][33];
    int bx = blockIdx.x * 32, by = blockIdx.y * 32;
#pragma unroll
    for (int i = 0; i < 32; i += 8)
        tile[threadIdx.y + i][threadIdx.x] =
            src[(size_t)(by + threadIdx.y + i) * C + bx + threadIdx.x];
    __syncthreads();
#pragma unroll
    for (int i = 0; i < 32; i += 8)
        dst[(size_t)(bx + threadIdx.y + i) * R + by + threadIdx.x] =
            rnaf(tile[threadIdx.x][threadIdx.y + i]);
}

// ===========================================================================
// tf32x2 mma GEMM, double-buffered with register prefetch.
// C[128,64] tile = A[128,512] @ Bt[64,512]^T, both K-major ld=512.
// K-stage 32, SMEM stride 36 (36 mod 32 = 4 -> conflict-free (4lg+lq)).
// 256 threads = 8 warps (2m x 4n); warp tile 64m x 16n; acc[4][2][4].
// SMEM: 2x(128+64)x36 floats = 55296 B -> 2 CTAs/SM.
// Loop: LDG(st+1) -> MMA(st) -> STS(st+1) -> sync.  LDG hides behind MMA.
// ===========================================================================
#define GK_STR 36
#define GA_BUF (128 * GK_STR)
#define GB_BUF (64 * GK_STR)
#define G_SMEM_BYTES ((2 * GA_BUF + 2 * GB_BUF) * 4)   /* 55296 */

#define MMA_GEMM_BODY(APTR, BTPTR)                                              \
    extern __shared__ float gsm[];                                              \
    float* sAb[2] = { gsm, gsm + GA_BUF };                                      \
    float* sBb[2] = { gsm + 2 * GA_BUF, gsm + 2 * GA_BUF + GB_BUF };            \
    const int t    = threadIdx.x;                                               \
    const int warp = t >> 5, lane = t & 31;                                     \
    const int wm   = warp >> 2, wn = warp & 3;                                  \
    const int lg   = lane >> 2, lq = lane & 3;                                  \
    const int row0 = blockIdx.y * 128, col0 = blockIdx.x * 64;                  \
    const float* Abase = (APTR) + (size_t)row0 * 512;                           \
    const float* Bbase = (BTPTR) + (size_t)col0 * 512;                          \
    float acc[4][2][4];                                                         \
    _Pragma("unroll") for (int i = 0; i < 4; i++)                               \
        _Pragma("unroll") for (int j = 0; j < 2; j++)                           \
            _Pragma("unroll") for (int c = 0; c < 4; c++) acc[i][j][c] = 0.f;   \
    float4 pa[4], pb[2];                                                        \
    _Pragma("unroll")                                                           \
    for (int i = 0; i < 4; i++) {                                               \
        int idx = i * 256 + t;                                                  \
        pa[i] = *reinterpret_cast<const float4*>(                               \
            Abase + (size_t)(idx >> 3) * 512 + (idx & 7) * 4);                  \
    }                                                                           \
    _Pragma("unroll")                                                           \
    for (int i = 0; i < 2; i++) {                                               \
        int idx = i * 256 + t;                                                  \
        pb[i] = *reinterpret_cast<const float4*>(                               \
            Bbase + (size_t)(idx >> 3) * 512 + (idx & 7) * 4);                  \
    }                                                                           \
    _Pragma("unroll")                                                           \
    for (int i = 0; i < 4; i++) {                                               \
        int idx = i * 256 + t;                                                  \
        *reinterpret_cast<float4*>(&sAb[0][(idx >> 3) * GK_STR + (idx & 7) * 4]) = pa[i]; \
    }                                                                           \
    _Pragma("unroll")                                                           \
    for (int i = 0; i < 2; i++) {                                               \
        int idx = i * 256 + t;                                                  \
        *reinterpret_cast<float4*>(&sBb[0][(idx >> 3) * GK_STR + (idx & 7) * 4]) = pb[i]; \
    }                                                                           \
    __syncthreads();                                                            \
    int buf = 0;                                                                \
    for (int st = 0; st < 16; st++) {                                           \
        const bool more = (st < 15);                                            \
        if (more) {                                                             \
            const int kofs = (st + 1) * 32;                                     \
            _Pragma("unroll")                                                   \
            for (int i = 0; i < 4; i++) {                                       \
                int idx = i * 256 + t;                                          \
                pa[i] = *reinterpret_cast<const float4*>(                       \
                    Abase + (size_t)(idx >> 3) * 512 + kofs + (idx & 7) * 4);   \
            }                                                                   \
            _Pragma("unroll")                                                   \
            for (int i = 0; i < 2; i++) {                                       \
                int idx = i * 256 + t;                                          \
                pb[i] = *reinterpret_cast<const float4*>(                       \
                    Bbase + (size_t)(idx >> 3) * 512 + kofs + (idx & 7) * 4);   \
            }                                                                   \
        }                                                                       \
        const float* sA = sAb[buf];                                             \
        const float* sB = sBb[buf];                                             \
        _Pragma("unroll")                                                       \
        for (int ks = 0; ks < 4; ks++) {                                        \
            const int k0 = ks * 8;                                              \
            uint32_t ahi[4][4], alo[4][4], bhi[2][2];                           \
            _Pragma("unroll")                                                   \
            for (int mf = 0; mf < 4; mf++) {                                    \
                int rA = wm * 64 + mf * 16 + lg;                                \
                float f0 = sA[rA * GK_STR + k0 + lq];                           \
                float f1 = sA[(rA + 8) * GK_STR + k0 + lq];                     \
                float f2 = sA[rA * GK_STR + k0 + lq + 4];                       \
                float f3 = sA[(rA + 8) * GK_STR + k0 + lq + 4];                 \
                ahi[mf][0] = tf32_rna(f0);                                      \
                alo[mf][0] = __float_as_uint(f0 - __uint_as_float(ahi[mf][0])); \
                ahi[mf][1] = tf32_rna(f1);                                      \
                alo[mf][1] = __float_as_uint(f1 - __uint_as_float(ahi[mf][1])); \
                ahi[mf][2] = tf32_rna(f2);                                      \
                alo[mf][2] = __float_as_uint(f2 - __uint_as_float(ahi[mf][2])); \
                ahi[mf][3] = tf32_rna(f3);                                      \
                alo[mf][3] = __float_as_uint(f3 - __uint_as_float(ahi[mf][3])); \
            }                                                                   \
            _Pragma("unroll")                                                   \
            for (int nf = 0; nf < 2; nf++) {                                    \
                int nb = wn * 16 + nf * 8 + lg;                                 \
                bhi[nf][0] = __float_as_uint(sB[nb * GK_STR + k0 + lq]);        \
                bhi[nf][1] = __float_as_uint(sB[nb * GK_STR + k0 + lq + 4]);    \
            }                                                                   \
            _Pragma("unroll")                                                   \
            for (int mf = 0; mf < 4; mf++)                                      \
                _Pragma("unroll")                                               \
                for (int nf = 0; nf < 2; nf++) {                                \
                    mma_tf32(acc[mf][nf], ahi[mf], bhi[nf]);                    \
                    mma_tf32(acc[mf][nf], alo[mf], bhi[nf]);                    \
                }                                                               \
        }                                                                       \
        if (more) {                                                             \
            _Pragma("unroll")                                                   \
            for (int i = 0; i < 4; i++) {                                       \
                int idx = i * 256 + t;                                          \
                *reinterpret_cast<float4*>(                                     \
                    &sAb[buf ^ 1][(idx >> 3) * GK_STR + (idx & 7) * 4]) = pa[i];\
            }                                                                   \
            _Pragma("unroll")                                                   \
            for (int i = 0; i < 2; i++) {                                       \
                int idx = i * 256 + t;                                          \
                *reinterpret_cast<float4*>(                                     \
                    &sBb[buf ^ 1][(idx >> 3) * GK_STR + (idx & 7) * 4]) = pb[i];\
            }                                                                   \
        }                                                                       \
        __syncthreads();                                                        \
        buf ^= 1;                                                               \
    }

// ---------------------------------------------------------------------------
// QKV GEMM (tf32x2 mma): q -> g_q (log2-scaled), k/v -> d_out [B,H,N,hd]
// col0 is 64-aligned -> s, h block-uniform; d = wn*16 + nf*8 + 2*lq.
// ---------------------------------------------------------------------------
__global__ __launch_bounds__(256, 2) void qkv_mma_kernel(
    const float* __restrict__ X, float* __restrict__ dout)
{
    MMA_GEMM_BODY(X, g_wt)

    const int s = col0 >> 9;              // 0=q,1=k,2=v (block-uniform)
    const int h = (col0 >> 6) & 7;        // block-uniform
#pragma unroll
    for (int mf = 0; mf < 4; mf++) {
        int m  = row0 + wm * 64 + mf * 16 + lg;
        int bb = m >> 11, n = m & 2047;
#pragma unroll
        for (int nf = 0; nf < 2; nf++) {
            int d = wn * 16 + nf * 8 + 2 * lq;
            size_t base0 = (((size_t)(bb * 8 + h)) * 2048 + n) * 64 + d;
            size_t base1 = base0 + 8 * 64;
            float2 v0 = make_float2(acc[mf][nf][0], acc[mf][nf][1]);
            float2 v1 = make_float2(acc[mf][nf][2], acc[mf][nf][3]);
            if (s == 0) {
                v0.x *= QSCALE_; v0.y *= QSCALE_;
                v1.x *= QSCALE_; v1.y *= QSCALE_;
                *reinterpret_cast<float2*>(&g_q[base0]) = v0;
                *reinterpret_cast<float2*>(&g_q[base1]) = v1;
            } else if (s == 1) {
                *reinterpret_cast<float2*>(dout + KOFF_ + base0) = v0;
                *reinterpret_cast<float2*>(dout + KOFF_ + base1) = v1;
            } else {
                *reinterpret_cast<float2*>(dout + VOFF_ + base0) = v0;
                *reinterpret_cast<float2*>(dout + VOFF_ + base1) = v1;
            }
        }
    }
}

// ---------------------------------------------------------------------------
// Proj GEMM (tf32x2 mma): g_ao @ W_proj + bias -> d_out[0..]
// ---------------------------------------------------------------------------
__global__ __launch_bounds__(256, 2) void proj_mma_kernel(
    const float* __restrict__ bias, float* __restrict__ dout)
{
    MMA_GEMM_BODY(g_ao, g_wtp)

#pragma unroll
    for (int mf = 0; mf < 4; mf++) {
        int m = row0 + wm * 64 + mf * 16 + lg;
#pragma unroll
        for (int nf = 0; nf < 2; nf++) {
            int gcol = col0 + wn * 16 + nf * 8 + 2 * lq;
            float bx = bias[gcol], by = bias[gcol + 1];
            float* d0 = dout + (size_t)m * 512 + gcol;
            float* d1 = dout + (size_t)(m + 8) * 512 + gcol;
            *reinterpret_cast<float2*>(d0) =
                make_float2(acc[mf][nf][0] + bx, acc[mf][nf][1] + by);
            *reinterpret_cast<float2*>(d1) =
                make_float2(acc[mf][nf][2] + bx, acc[mf][nf][3] + by);
        }
    }
}

// ===========================================================================
// Flash attention: mma.sync tf32. QK^T = x1, PV = x1, rounding at SMEM
// stores. (verified R11 — byte-identical)
// ===========================================================================
#define SQ_STR 68
#define SK_STR 68
#define SV_STR 72
#define SP_STR 132
#define AT_FLOATS (64*SQ_STR + 8704 + 128*SV_STR + 4*64)
#define AT_BYTES  (AT_FLOATS * 4)

__global__ __launch_bounds__(256, 2) void attn_mma_kernel(const float* __restrict__ dkv)
{
    extern __shared__ float sm[];
    float* sQ   = sm;                       // [64][68], tf32-rounded
    float* sK   = sm + 64 * SQ_STR;         // [128][68], aliased by sP[64][132]
    float* sP   = sK;
    float* sV   = sK + 8704;                // [128][72]
    float* sRed = sV + 128 * SV_STR;        // [4][64]

    const int t    = threadIdx.x;
    const int warp = t >> 5, lane = t & 31;
    const int wm   = warp >> 2, wn = warp & 3;
    const int lg   = lane >> 2, lq = lane & 3;
    const int qt   = blockIdx.x, h = blockIdx.y, bb = blockIdx.z;

    const size_t bh = (size_t)(bb * 8 + h);
    const float* qb = g_q + (bh * 2048 + (size_t)qt * 64) * 64;
    const float* kb = dkv + KOFF_ + bh * 2048 * 64;
    const float* vb = dkv + VOFF_ + bh * 2048 * 64;

    // load Q tile [64][64], tf32-round once
#pragma unroll 4
    for (int i = t; i < 1024; i += 256) {
        int m = i >> 4, d4 = (i & 15) * 4;
        float4 v = *reinterpret_cast<const float4*>(qb + m * 64 + d4);
        *reinterpret_cast<float4*>(&sQ[m * SQ_STR + d4]) = rna4(v);
    }

    float o[2][2][4];
    float lsum[2][2];
#pragma unroll
    for (int mi = 0; mi < 2; mi++) {
        lsum[mi][0] = 0.f; lsum[mi][1] = 0.f;
#pragma unroll
        for (int nf = 0; nf < 2; nf++)
#pragma unroll
            for (int c = 0; c < 4; c++) o[mi][nf][c] = 0.f;
    }

    for (int j0 = 0; j0 < 2048; j0 += 128) {
        __syncthreads();
        // load K/V tiles, tf32-round at store
#pragma unroll 4
        for (int i = t; i < 2048; i += 256) {
            int j = i >> 4, d4 = (i & 15) * 4;
            float4 kv = *reinterpret_cast<const float4*>(kb + (size_t)(j0 + j) * 64 + d4);
            float4 vv = *reinterpret_cast<const float4*>(vb + (size_t)(j0 + j) * 64 + d4);
            *reinterpret_cast<float4*>(&sK[j * SK_STR + d4]) = rna4(kv);
            *reinterpret_cast<float4*>(&sV[j * SV_STR + d4]) = rna4(vv);
        }
        __syncthreads();

        float s[2][4][4];
#pragma unroll
        for (int mi = 0; mi < 2; mi++)
#pragma unroll
            for (int ni = 0; ni < 4; ni++)
#pragma unroll
                for (int c = 0; c < 4; c++) s[mi][ni][c] = 0.f;

#pragma unroll
        for (int ks = 0; ks < 8; ks++) {
            const int k0 = ks * 8;
            uint32_t a[2][4], b[4][2];
#pragma unroll
            for (int mi = 0; mi < 2; mi++) {
                int rA = wm * 32 + mi * 16 + lg;
                a[mi][0] = __float_as_uint(sQ[rA * SQ_STR + k0 + lq]);
                a[mi][1] = __float_as_uint(sQ[(rA + 8) * SQ_STR + k0 + lq]);
                a[mi][2] = __float_as_uint(sQ[rA * SQ_STR + k0 + lq + 4]);
                a[mi][3] = __float_as_uint(sQ[(rA + 8) * SQ_STR + k0 + lq + 4]);
            }
#pragma unroll
            for (int ni = 0; ni < 4; ni++) {
                int nb = wn * 32 + ni * 8 + lg;
                b[ni][0] = __float_as_uint(sK[nb * SK_STR + k0 + lq]);
                b[ni][1] = __float_as_uint(sK[nb * SK_STR + k0 + lq + 4]);
            }
#pragma unroll
            for (int mi = 0; mi < 2; mi++)
#pragma unroll
                for (int ni = 0; ni < 4; ni++)
                    mma_tf32(s[mi][ni], a[mi], b[ni]);
        }
        __syncthreads();

        // P = 2^S, tf32-rounded at store; lsum accumulates the ROUNDED P
#pragma unroll
        for (int mi = 0; mi < 2; mi++) {
            int row = wm * 32 + mi * 16 + lg;
#pragma unroll
            for (int ni = 0; ni < 4; ni++) {
                float p0 = rnaf(fexp2(s[mi][ni][0]));
                float p1 = rnaf(fexp2(s[mi][ni][1]));
                float p2 = rnaf(fexp2(s[mi][ni][2]));
                float p3 = rnaf(fexp2(s[mi][ni][3]));
                lsum[mi][0] += p0 + p1;
                lsum[mi][1] += p2 + p3;
                int col = wn * 32 + ni * 8 + 2 * lq;
                *reinterpret_cast<float2*>(&sP[row * SP_STR + col]) = make_float2(p0, p1);
                *reinterpret_cast<float2*>(&sP[(row + 8) * SP_STR + col]) = make_float2(p2, p3);
            }
        }
        __syncthreads();

#pragma unroll
        for (int kk = 0; kk < 16; kk++) {
            const int k0 = kk * 8;
            uint32_t phi[2][4], bv[2][2];
#pragma unroll
            for (int mi = 0; mi < 2; mi++) {
                int rA = wm * 32 + mi * 16 + lg;
                phi[mi][0] = __float_as_uint(sP[rA * SP_STR + k0 + lq]);
                phi[mi][1] = __float_as_uint(sP[(rA + 8) * SP_STR + k0 + lq]);
                phi[mi][2] = __float_as_uint(sP[rA * SP_STR + k0 + lq + 4]);
                phi[mi][3] = __float_as_uint(sP[(rA + 8) * SP_STR + k0 + lq + 4]);
            }
#pragma unroll
            for (int nf = 0; nf < 2; nf++) {
                int nb = wn * 16 + nf * 8 + lg;
                bv[nf][0] = __float_as_uint(sV[(k0 + lq) * SV_STR + nb]);
                bv[nf][1] = __float_as_uint(sV[(k0 + lq + 4) * SV_STR + nb]);
            }
#pragma unroll
            for (int mi = 0; mi < 2; mi++)
#pragma unroll
                for (int nf = 0; nf < 2; nf++)
                    mma_tf32(o[mi][nf], phi[mi], bv[nf]);
        }
    }

#pragma unroll
    for (int mi = 0; mi < 2; mi++)
#pragma unroll
        for (int hf = 0; hf < 2; hf++) {
            float v = lsum[mi][hf];
            v += __shfl_xor_sync(0xffffffffu, v, 1);
            v += __shfl_xor_sync(0xffffffffu, v, 2);
            lsum[mi][hf] = v;
            if (lq == 0)
                sRed[wn * 64 + wm * 32 + mi * 16 + lg + 8 * hf] = v;
        }
    __syncthreads();

#pragma unroll
    for (int mi = 0; mi < 2; mi++) {
        int row = wm * 32 + mi * 16 + lg;
        float l0 = sRed[0 * 64 + row] + sRed[1 * 64 + row] +
                   sRed[2 * 64 + row] + sRed[3 * 64 + row];
        float l1 = sRed[0 * 64 + row + 8] + sRed[1 * 64 + row + 8] +
                   sRed[2 * 64 + row + 8] + sRed[3 * 64 + row + 8];
        float inv0 = __fdividef(1.f, l0);
        float inv1 = __fdividef(1.f, l1);
        int n0 = qt * 64 + row;
#pragma unroll
        for (int nf = 0; nf < 2; nf++) {
            int col = h * 64 + wn * 16 + nf * 8 + 2 * lq;
            float* d0 = g_ao + ((size_t)bb * 2048 + n0) * 512 + col;
            float* d1 = g_ao + ((size_t)bb * 2048 + n0 + 8) * 512 + col;
            *reinterpret_cast<float2*>(d0) =
                make_float2(o[mi][nf][0] * inv0, o[mi][nf][1] * inv0);
            *reinterpret_cast<float2*>(d1) =
                make_float2(o[mi][nf][2] * inv1, o[mi][nf][3] * inv1);
        }
    }
}

// ===========================================================================
extern "C" void kernel_launch(void* const* d_in, const int* in_sizes, int n_in,
                              void* d_out, int out_size)
{
    const float* x     = (const float*)d_in[0];
    const float* wqkv  = (const float*)d_in[1];
    const float* wproj = (const float*)d_in[2];
    const float* bproj = (const float*)d_in[3];
    float* out = (float*)d_out;

    cudaFuncSetAttribute(attn_mma_kernel,
                         cudaFuncAttributeMaxDynamicSharedMemorySize, AT_BYTES);
    cudaFuncSetAttribute(qkv_mma_kernel,
                         cudaFuncAttributeMaxDynamicSharedMemorySize, G_SMEM_BYTES);
    cudaFuncSetAttribute(proj_mma_kernel,
                         cudaFuncAttributeMaxDynamicSharedMemorySize, G_SMEM_BYTES);

    transpose_kernel<<<dim3(48, 16), dim3(32, 8)>>>(wqkv,  0, 512, 1536);
    transpose_kernel<<<dim3(16, 16), dim3(32, 8)>>>(wproj, 1, 512, 512);

    qkv_mma_kernel <<<dim3(24, 64), 256, G_SMEM_BYTES>>>(x, out);
    attn_mma_kernel<<<dim3(32, 8, 4), 256, AT_BYTES>>>(out);
    proj_mma_kernel<<<dim3(8, 64), 256, G_SMEM_BYTES>>>(bproj, out);
}

// round 13
// speedup vs baseline: 1.1435x; 1.1435x over previous
#include <cuda_runtime.h>
#include <cstdint>

#define BB_  4
#define NN_  2048
#define CC_  512
#define HH_  8
#define HD_  64
// q pre-scale: (1/sqrt(64)) * log2(e)  -> scores arrive in log2 domain
#define QSCALE_ 0.18033688011112042f

// d_out layout: [ out (B*N*C) | k (B*H*N*hd) | v (B*H*N*hd) ]
#define KOFF_ (4u * 2048u * 512u)
#define VOFF_ (8u * 2048u * 512u)

// scratch
__device__ float g_q  [BB_ * HH_ * NN_ * HD_];   // pre-scaled q (log2 domain)
__device__ float g_ao [BB_ * NN_ * CC_];         // attention out [B,N,C]
__device__ float g_wt [1536 * 512];              // W_qkv^T  [N][K], tf32-rounded
__device__ float g_wtp[512 * 512];               // W_proj^T [N][K], tf32-rounded

// ===========================================================================
// m16n8k8 tf32 mma (base ISA, works on plain sm_103 target)
// ===========================================================================
__device__ __forceinline__ void mma_tf32(float (&d)[4], const uint32_t (&a)[4],
                                         const uint32_t (&b)[2]) {
    asm volatile(
        "mma.sync.aligned.m16n8k8.row.col.f32.tf32.tf32.f32 "
        "{%0,%1,%2,%3}, {%4,%5,%6,%7}, {%8,%9}, {%0,%1,%2,%3};"
        : "+f"(d[0]), "+f"(d[1]), "+f"(d[2]), "+f"(d[3])
        : "r"(a[0]), "r"(a[1]), "r"(a[2]), "r"(a[3]), "r"(b[0]), "r"(b[1]));
}

__device__ __forceinline__ uint32_t tf32_rna(float x) {
    uint32_t r;
    asm("cvt.rna.tf32.f32 %0, %1;" : "=r"(r) : "f"(x));
    return r;
}
__device__ __forceinline__ float rnaf(float x) {
    return __uint_as_float(tf32_rna(x));
}
__device__ __forceinline__ float4 rna4(float4 v) {
    v.x = rnaf(v.x); v.y = rnaf(v.y); v.z = rnaf(v.z); v.w = rnaf(v.w);
    return v;
}
__device__ __forceinline__ uint32_t smem_u32(const void* p) {
    uint32_t a;
    asm("{ .reg .u64 t; cvta.to.shared.u64 t, %1; cvt.u32.u64 %0, t; }"
        : "=r"(a) : "l"(p));
    return a;
}

#define CP_ASYNC16(saddr, gptr) \
    asm volatile("cp.async.ca.shared.global [%0], [%1], 16;" \
        :: "r"(saddr), "l"(gptr) : "memory")
#define CP_COMMIT() \
    asm volatile("cp.async.commit_group;" ::: "memory")
#define CP_WAIT0() \
    asm volatile("cp.async.wait_group 0;" ::: "memory")

// fast 2^t on fma/alu pipes only (no MUFU). t >= -100 clamped; |err| ~ 3e-6.
__device__ __forceinline__ float fexp2(float t) {
    t = fmaxf(t, -100.f);
    float z = t + 12582912.f;
    int   n = __float_as_int(z) - 0x4B400000;
    float f = t - (z - 12582912.f);
    float p =        1.3333558e-3f;
    p = fmaf(p, f, 9.6181291e-3f);
    p = fmaf(p, f, 5.5504109e-2f);
    p = fmaf(p, f, 2.4022651e-1f);
    p = fmaf(p, f, 6.9314718e-1f);
    p = fmaf(p, f, 1.0f);
    return __int_as_float(__float_as_int(p) + (n << 23));
}

// ===========================================================================
// W transpose + tf32 pre-round: src[R][C] -> dst[C][R] (dst in device code)
// which: 0 -> g_wt, 1 -> g_wtp
// ===========================================================================
__global__ void transpose_kernel(const float* __restrict__ src,
                                 int which, int R, int C)
{
    float* dst = which ? g_wtp : g_wt;
    __shared__ float tile[32][33];
    int bx = blockIdx.x * 32, by = blockIdx.y * 32;
#pragma unroll
    for (int i = 0; i < 32; i += 8)
        tile[threadIdx.y + i][threadIdx.x] =
            src[(size_t)(by + threadIdx.y + i) * C + bx + threadIdx.x];
    __syncthreads();
#pragma unroll
    for (int i = 0; i < 32; i += 8)
        dst[(size_t)(bx + threadIdx.y + i) * R + by + threadIdx.x] =
            rnaf(tile[threadIdx.x][threadIdx.y + i]);
}

// ===========================================================================
// tf32x2 mma GEMM, cp.async double-buffered (no register prefetch).
// C[128,128] tile = A[128,512] @ Bt[128,512]^T, both K-major ld=512.
// K-stage 32, SMEM stride 36 (36 mod 32 = 4 -> conflict-free (4lg+lq);
// fragment pattern correctness-verified in R12). 256 threads = 8 warps
// (2m x 4n); warp tile 64m x 32n; acc[4][4][4] (R11-verified shape).
// SMEM: 2 x (128A + 128B) x 36 floats = 73728 B -> 2 CTAs/SM.
// Per stage: wait_group 0 -> sync -> cp.async(st+1) -> MMA(st).
// ===========================================================================
#define GK_STR 36
#define G_BUF  (128 * GK_STR)                  /* floats per operand buffer */
#define G_SMEM_BYTES (4 * G_BUF * 4)           /* 73728 */

#define G_ISSUE_STAGE(kofs, bufb)                                               \
    do {                                                                        \
        _Pragma("unroll")                                                       \
        for (int i = 0; i < 4; i++) {                                           \
            int idx = i * 256 + t;                                              \
            int row = idx >> 3, c4 = (idx & 7) * 4;                             \
            CP_ASYNC16(sbase + (uint32_t)((bufb) * G_BUF + row * GK_STR + c4) * 4u, \
                       Abase + (size_t)row * 512 + (kofs) + c4);                \
            CP_ASYNC16(sbase + (uint32_t)(2 * G_BUF + (bufb) * G_BUF + row * GK_STR + c4) * 4u, \
                       Bbase + (size_t)row * 512 + (kofs) + c4);                \
        }                                                                       \
        CP_COMMIT();                                                            \
    } while (0)

#define MMA_GEMM_BODY(APTR, BTPTR)                                              \
    extern __shared__ float gsm[];                                              \
    const int t    = threadIdx.x;                                               \
    const int warp = t >> 5, lane = t & 31;                                     \
    const int wm   = warp >> 2, wn = warp & 3;                                  \
    const int lg   = lane >> 2, lq = lane & 3;                                  \
    const int row0 = blockIdx.y * 128, col0 = blockIdx.x * 128;                 \
    const float* Abase = (APTR) + (size_t)row0 * 512;                           \
    const float* Bbase = (BTPTR) + (size_t)col0 * 512;                          \
    const uint32_t sbase = smem_u32(gsm);                                       \
    float acc[4][4][4];                                                         \
    _Pragma("unroll") for (int i = 0; i < 4; i++)                               \
        _Pragma("unroll") for (int j = 0; j < 4; j++)                           \
            _Pragma("unroll") for (int c = 0; c < 4; c++) acc[i][j][c] = 0.f;   \
    G_ISSUE_STAGE(0, 0);                                                        \
    int buf = 0;                                                                \
    for (int st = 0; st < 16; st++) {                                           \
        CP_WAIT0();                                                             \
        __syncthreads();                                                        \
        if (st < 15) G_ISSUE_STAGE((st + 1) * 32, buf ^ 1);                     \
        const float* sA = gsm + buf * G_BUF;                                    \
        const float* sB = gsm + 2 * G_BUF + buf * G_BUF;                        \
        _Pragma("unroll")                                                       \
        for (int ks = 0; ks < 4; ks++) {                                        \
            const int k0 = ks * 8;                                              \
            uint32_t ahi[4][4], alo[4][4], bhi[4][2];                           \
            _Pragma("unroll")                                                   \
            for (int mf = 0; mf < 4; mf++) {                                    \
                int rA = wm * 64 + mf * 16 + lg;                                \
                float f0 = sA[rA * GK_STR + k0 + lq];                           \
                float f1 = sA[(rA + 8) * GK_STR + k0 + lq];                     \
                float f2 = sA[rA * GK_STR + k0 + lq + 4];                       \
                float f3 = sA[(rA + 8) * GK_STR + k0 + lq + 4];                 \
                ahi[mf][0] = tf32_rna(f0);                                      \
                alo[mf][0] = __float_as_uint(f0 - __uint_as_float(ahi[mf][0])); \
                ahi[mf][1] = tf32_rna(f1);                                      \
                alo[mf][1] = __float_as_uint(f1 - __uint_as_float(ahi[mf][1])); \
                ahi[mf][2] = tf32_rna(f2);                                      \
                alo[mf][2] = __float_as_uint(f2 - __uint_as_float(ahi[mf][2])); \
                ahi[mf][3] = tf32_rna(f3);                                      \
                alo[mf][3] = __float_as_uint(f3 - __uint_as_float(ahi[mf][3])); \
            }                                                                   \
            _Pragma("unroll")                                                   \
            for (int nf = 0; nf < 4; nf++) {                                    \
                int nb = wn * 32 + nf * 8 + lg;                                 \
                bhi[nf][0] = __float_as_uint(sB[nb * GK_STR + k0 + lq]);        \
                bhi[nf][1] = __float_as_uint(sB[nb * GK_STR + k0 + lq + 4]);    \
            }                                                                   \
            _Pragma("unroll")                                                   \
            for (int mf = 0; mf < 4; mf++)                                      \
                _Pragma("unroll")                                               \
                for (int nf = 0; nf < 4; nf++) {                                \
                    mma_tf32(acc[mf][nf], ahi[mf], bhi[nf]);                    \
                    mma_tf32(acc[mf][nf], alo[mf], bhi[nf]);                    \
                }                                                               \
        }                                                                       \
        buf ^= 1;                                                               \
    }

// ---------------------------------------------------------------------------
// QKV GEMM (tf32x2 mma): q -> g_q (log2-scaled), k/v -> d_out [B,H,N,hd]
// (epilogue verbatim from verified R11)
// ---------------------------------------------------------------------------
__global__ __launch_bounds__(256, 2) void qkv_mma_kernel(
    const float* __restrict__ X, float* __restrict__ dout)
{
    MMA_GEMM_BODY(X, g_wt)

    const int s = col0 >> 9;                       // 0=q,1=k,2=v (block-uniform)
    const int h = ((col0 + wn * 32) >> 6) & 7;     // warp-uniform
#pragma unroll
    for (int mf = 0; mf < 4; mf++) {
        int m  = row0 + wm * 64 + mf * 16 + lg;
        int bb = m >> 11, n = m & 2047;
#pragma unroll
        for (int nf = 0; nf < 4; nf++) {
            int d = ((col0 + wn * 32 + nf * 8) & 63) + 2 * lq;
            size_t base0 = (((size_t)(bb * 8 + h)) * 2048 + n) * 64 + d;
            size_t base1 = base0 + 8 * 64;
            float2 v0 = make_float2(acc[mf][nf][0], acc[mf][nf][1]);
            float2 v1 = make_float2(acc[mf][nf][2], acc[mf][nf][3]);
            if (s == 0) {
                v0.x *= QSCALE_; v0.y *= QSCALE_;
                v1.x *= QSCALE_; v1.y *= QSCALE_;
                *reinterpret_cast<float2*>(&g_q[base0]) = v0;
                *reinterpret_cast<float2*>(&g_q[base1]) = v1;
            } else if (s == 1) {
                *reinterpret_cast<float2*>(dout + KOFF_ + base0) = v0;
                *reinterpret_cast<float2*>(dout + KOFF_ + base1) = v1;
            } else {
                *reinterpret_cast<float2*>(dout + VOFF_ + base0) = v0;
                *reinterpret_cast<float2*>(dout + VOFF_ + base1) = v1;
            }
        }
    }
}

// ---------------------------------------------------------------------------
// Proj GEMM (tf32x2 mma): g_ao @ W_proj + bias -> d_out[0..]
// ---------------------------------------------------------------------------
__global__ __launch_bounds__(256, 2) void proj_mma_kernel(
    const float* __restrict__ bias, float* __restrict__ dout)
{
    MMA_GEMM_BODY(g_ao, g_wtp)

#pragma unroll
    for (int mf = 0; mf < 4; mf++) {
        int m = row0 + wm * 64 + mf * 16 + lg;
#pragma unroll
        for (int nf = 0; nf < 4; nf++) {
            int gcol = col0 + wn * 32 + nf * 8 + 2 * lq;
            float bx = bias[gcol], by = bias[gcol + 1];
            float* d0 = dout + (size_t)m * 512 + gcol;
            float* d1 = dout + (size_t)(m + 8) * 512 + gcol;
            *reinterpret_cast<float2*>(d0) =
                make_float2(acc[mf][nf][0] + bx, acc[mf][nf][1] + by);
            *reinterpret_cast<float2*>(d1) =
                make_float2(acc[mf][nf][2] + bx, acc[mf][nf][3] + by);
        }
    }
}

// ===========================================================================
// Flash attention: mma.sync tf32. QK^T = x1, PV = x1, rounding at SMEM
// stores. (verified R11 — byte-identical)
// ===========================================================================
#define SQ_STR 68
#define SK_STR 68
#define SV_STR 72
#define SP_STR 132
#define AT_FLOATS (64*SQ_STR + 8704 + 128*SV_STR + 4*64)
#define AT_BYTES  (AT_FLOATS * 4)

__global__ __launch_bounds__(256, 2) void attn_mma_kernel(const float* __restrict__ dkv)
{
    extern __shared__ float sm[];
    float* sQ   = sm;                       // [64][68], tf32-rounded
    float* sK   = sm + 64 * SQ_STR;         // [128][68], aliased by sP[64][132]
    float* sP   = sK;
    float* sV   = sK + 8704;                // [128][72]
    float* sRed = sV + 128 * SV_STR;        // [4][64]

    const int t    = threadIdx.x;
    const int warp = t >> 5, lane = t & 31;
    const int wm   = warp >> 2, wn = warp & 3;
    const int lg   = lane >> 2, lq = lane & 3;
    const int qt   = blockIdx.x, h = blockIdx.y, bb = blockIdx.z;

    const size_t bh = (size_t)(bb * 8 + h);
    const float* qb = g_q + (bh * 2048 + (size_t)qt * 64) * 64;
    const float* kb = dkv + KOFF_ + bh * 2048 * 64;
    const float* vb = dkv + VOFF_ + bh * 2048 * 64;

    // load Q tile [64][64], tf32-round once
#pragma unroll 4
    for (int i = t; i < 1024; i += 256) {
        int m = i >> 4, d4 = (i & 15) * 4;
        float4 v = *reinterpret_cast<const float4*>(qb + m * 64 + d4);
        *reinterpret_cast<float4*>(&sQ[m * SQ_STR + d4]) = rna4(v);
    }

    float o[2][2][4];
    float lsum[2][2];
#pragma unroll
    for (int mi = 0; mi < 2; mi++) {
        lsum[mi][0] = 0.f; lsum[mi][1] = 0.f;
#pragma unroll
        for (int nf = 0; nf < 2; nf++)
#pragma unroll
            for (int c = 0; c < 4; c++) o[mi][nf][c] = 0.f;
    }

    for (int j0 = 0; j0 < 2048; j0 += 128) {
        __syncthreads();
        // load K/V tiles, tf32-round at store
#pragma unroll 4
        for (int i = t; i < 2048; i += 256) {
            int j = i >> 4, d4 = (i & 15) * 4;
            float4 kv = *reinterpret_cast<const float4*>(kb + (size_t)(j0 + j) * 64 + d4);
            float4 vv = *reinterpret_cast<const float4*>(vb + (size_t)(j0 + j) * 64 + d4);
            *reinterpret_cast<float4*>(&sK[j * SK_STR + d4]) = rna4(kv);
            *reinterpret_cast<float4*>(&sV[j * SV_STR + d4]) = rna4(vv);
        }
        __syncthreads();

        float s[2][4][4];
#pragma unroll
        for (int mi = 0; mi < 2; mi++)
#pragma unroll
            for (int ni = 0; ni < 4; ni++)
#pragma unroll
                for (int c = 0; c < 4; c++) s[mi][ni][c] = 0.f;

#pragma unroll
        for (int ks = 0; ks < 8; ks++) {
            const int k0 = ks * 8;
            uint32_t a[2][4], b[4][2];
#pragma unroll
            for (int mi = 0; mi < 2; mi++) {
                int rA = wm * 32 + mi * 16 + lg;
                a[mi][0] = __float_as_uint(sQ[rA * SQ_STR + k0 + lq]);
                a[mi][1] = __float_as_uint(sQ[(rA + 8) * SQ_STR + k0 + lq]);
                a[mi][2] = __float_as_uint(sQ[rA * SQ_STR + k0 + lq + 4]);
                a[mi][3] = __float_as_uint(sQ[(rA + 8) * SQ_STR + k0 + lq + 4]);
            }
#pragma unroll
            for (int ni = 0; ni < 4; ni++) {
                int nb = wn * 32 + ni * 8 + lg;
                b[ni][0] = __float_as_uint(sK[nb * SK_STR + k0 + lq]);
                b[ni][1] = __float_as_uint(sK[nb * SK_STR + k0 + lq + 4]);
            }
#pragma unroll
            for (int mi = 0; mi < 2; mi++)
#pragma unroll
                for (int ni = 0; ni < 4; ni++)
                    mma_tf32(s[mi][ni], a[mi], b[ni]);
        }
        __syncthreads();

        // P = 2^S, tf32-rounded at store; lsum accumulates the ROUNDED P
#pragma unroll
        for (int mi = 0; mi < 2; mi++) {
            int row = wm * 32 + mi * 16 + lg;
#pragma unroll
            for (int ni = 0; ni < 4; ni++) {
                float p0 = rnaf(fexp2(s[mi][ni][0]));
                float p1 = rnaf(fexp2(s[mi][ni][1]));
                float p2 = rnaf(fexp2(s[mi][ni][2]));
                float p3 = rnaf(fexp2(s[mi][ni][3]));
                lsum[mi][0] += p0 + p1;
                lsum[mi][1] += p2 + p3;
                int col = wn * 32 + ni * 8 + 2 * lq;
                *reinterpret_cast<float2*>(&sP[row * SP_STR + col]) = make_float2(p0, p1);
                *reinterpret_cast<float2*>(&sP[(row + 8) * SP_STR + col]) = make_float2(p2, p3);
            }
        }
        __syncthreads();

#pragma unroll
        for (int kk = 0; kk < 16; kk++) {
            const int k0 = kk * 8;
            uint32_t phi[2][4], bv[2][2];
#pragma unroll
            for (int mi = 0; mi < 2; mi++) {
                int rA = wm * 32 + mi * 16 + lg;
                phi[mi][0] = __float_as_uint(sP[rA * SP_STR + k0 + lq]);
                phi[mi][1] = __float_as_uint(sP[(rA + 8) * SP_STR + k0 + lq]);
                phi[mi][2] = __float_as_uint(sP[rA * SP_STR + k0 + lq + 4]);
                phi[mi][3] = __float_as_uint(sP[(rA + 8) * SP_STR + k0 + lq + 4]);
            }
#pragma unroll
            for (int nf = 0; nf < 2; nf++) {
                int nb = wn * 16 + nf * 8 + lg;
                bv[nf][0] = __float_as_uint(sV[(k0 + lq) * SV_STR + nb]);
                bv[nf][1] = __float_as_uint(sV[(k0 + lq + 4) * SV_STR + nb]);
            }
#pragma unroll
            for (int mi = 0; mi < 2; mi++)
#pragma unroll
                for (int nf = 0; nf < 2; nf++)
                    mma_tf32(o[mi][nf], phi[mi], bv[nf]);
        }
    }

#pragma unroll
    for (int mi = 0; mi < 2; mi++)
#pragma unroll
        for (int hf = 0; hf < 2; hf++) {
            float v = lsum[mi][hf];
            v += __shfl_xor_sync(0xffffffffu, v, 1);
            v += __shfl_xor_sync(0xffffffffu, v, 2);
            lsum[mi][hf] = v;
            if (lq == 0)
                sRed[wn * 64 + wm * 32 + mi * 16 + lg + 8 * hf] = v;
        }
    __syncthreads();

#pragma unroll
    for (int mi = 0; mi < 2; mi++) {
        int row = wm * 32 + mi * 16 + lg;
        float l0 = sRed[0 * 64 + row] + sRed[1 * 64 + row] +
                   sRed[2 * 64 + row] + sRed[3 * 64 + row];
        float l1 = sRed[0 * 64 + row + 8] + sRed[1 * 64 + row + 8] +
                   sRed[2 * 64 + row + 8] + sRed[3 * 64 + row + 8];
        float inv0 = __fdividef(1.f, l0);
        float inv1 = __fdividef(1.f, l1);
        int n0 = qt * 64 + row;
#pragma unroll
        for (int nf = 0; nf < 2; nf++) {
            int col = h * 64 + wn * 16 + nf * 8 + 2 * lq;
            float* d0 = g_ao + ((size_t)bb * 2048 + n0) * 512 + col;
            float* d1 = g_ao + ((size_t)bb * 2048 + n0 + 8) * 512 + col;
            *reinterpret_cast<float2*>(d0) =
                make_float2(o[mi][nf][0] * inv0, o[mi][nf][1] * inv0);
            *reinterpret_cast<float2*>(d1) =
                make_float2(o[mi][nf][2] * inv1, o[mi][nf][3] * inv1);
        }
    }
}

// ===========================================================================
extern "C" void kernel_launch(void* const* d_in, const int* in_sizes, int n_in,
                              void* d_out, int out_size)
{
    const float* x     = (const float*)d_in[0];
    const float* wqkv  = (const float*)d_in[1];
    const float* wproj = (const float*)d_in[2];
    const float* bproj = (const float*)d_in[3];
    float* out = (float*)d_out;

    cudaFuncSetAttribute(attn_mma_kernel,
                         cudaFuncAttributeMaxDynamicSharedMemorySize, AT_BYTES);
    cudaFuncSetAttribute(qkv_mma_kernel,
                         cudaFuncAttributeMaxDynamicSharedMemorySize, G_SMEM_BYTES);
    cudaFuncSetAttribute(proj_mma_kernel,
                         cudaFuncAttributeMaxDynamicSharedMemorySize, G_SMEM_BYTES);

    transpose_kernel<<<dim3(48, 16), dim3(32, 8)>>>(wqkv,  0, 512, 1536);
    transpose_kernel<<<dim3(16, 16), dim3(32, 8)>>>(wproj, 1, 512, 512);

    qkv_mma_kernel <<<dim3(12, 64), 256, G_SMEM_BYTES>>>(x, out);
    attn_mma_kernel<<<dim3(32, 8, 4), 256, AT_BYTES>>>(out);
    proj_mma_kernel<<<dim3(4, 64), 256, G_SMEM_BYTES>>>(bproj, out);
}

// round 14
// speedup vs baseline: 1.3466x; 1.1776x over previous
#include <cuda_runtime.h>
#include <cstdint>

#define BB_  4
#define NN_  2048
#define CC_  512
#define HH_  8
#define HD_  64
// q pre-scale: (1/sqrt(64)) * log2(e)  -> scores arrive in log2 domain
#define QSCALE_ 0.18033688011112042f

// d_out layout: [ out (B*N*C) | k (B*H*N*hd) | v (B*H*N*hd) ]
#define KOFF_ (4u * 2048u * 512u)
#define VOFF_ (8u * 2048u * 512u)

// scratch
__device__ float g_q  [BB_ * HH_ * NN_ * HD_];   // pre-scaled q, tf32-rounded
__device__ float g_ao [BB_ * NN_ * CC_];         // attention out, tf32-rounded
__device__ float g_xr [BB_ * NN_ * CC_];         // X, tf32-rounded
__device__ float g_wt [1536 * 512];              // W_qkv^T  [N][K], tf32-rounded
__device__ float g_wtp[512 * 512];               // W_proj^T [N][K], tf32-rounded

// ===========================================================================
// m16n8k8 tf32 mma (base ISA, works on plain sm_103 target)
// ===========================================================================
__device__ __forceinline__ void mma_tf32(float (&d)[4], const uint32_t (&a)[4],
                                         const uint32_t (&b)[2]) {
    asm volatile(
        "mma.sync.aligned.m16n8k8.row.col.f32.tf32.tf32.f32 "
        "{%0,%1,%2,%3}, {%4,%5,%6,%7}, {%8,%9}, {%0,%1,%2,%3};"
        : "+f"(d[0]), "+f"(d[1]), "+f"(d[2]), "+f"(d[3])
        : "r"(a[0]), "r"(a[1]), "r"(a[2]), "r"(a[3]), "r"(b[0]), "r"(b[1]));
}

__device__ __forceinline__ uint32_t tf32_rna(float x) {
    uint32_t r;
    asm("cvt.rna.tf32.f32 %0, %1;" : "=r"(r) : "f"(x));
    return r;
}
__device__ __forceinline__ float rnaf(float x) {
    return __uint_as_float(tf32_rna(x));
}
__device__ __forceinline__ float4 rna4(float4 v) {
    v.x = rnaf(v.x); v.y = rnaf(v.y); v.z = rnaf(v.z); v.w = rnaf(v.w);
    return v;
}
__device__ __forceinline__ uint32_t smem_u32(const void* p) {
    uint32_t a;
    asm("{ .reg .u64 t; cvta.to.shared.u64 t, %1; cvt.u32.u64 %0, t; }"
        : "=r"(a) : "l"(p));
    return a;
}

#define CP_ASYNC16(saddr, gptr) \
    asm volatile("cp.async.ca.shared.global [%0], [%1], 16;" \
        :: "r"(saddr), "l"(gptr) : "memory")
#define CP_COMMIT() \
    asm volatile("cp.async.commit_group;" ::: "memory")
#define CP_WAIT0() \
    asm volatile("cp.async.wait_group 0;" ::: "memory")

// fast 2^t on fma/alu pipes only (no MUFU). t >= -100 clamped; |err| ~ 3e-6.
__device__ __forceinline__ float fexp2(float t) {
    t = fmaxf(t, -100.f);
    float z = t + 12582912.f;
    int   n = __float_as_int(z) - 0x4B400000;
    float f = t - (z - 12582912.f);
    float p =        1.3333558e-3f;
    p = fmaf(p, f, 9.6181291e-3f);
    p = fmaf(p, f, 5.5504109e-2f);
    p = fmaf(p, f, 2.4022651e-1f);
    p = fmaf(p, f, 6.9314718e-1f);
    p = fmaf(p, f, 1.0f);
    return __int_as_float(__float_as_int(p) + (n << 23));
}

// ===========================================================================
// round_x: g_xr = tf32_rna(X)  (grid-stride float4)
// ===========================================================================
__global__ void round_x_kernel(const float* __restrict__ X)
{
    int i = blockIdx.x * blockDim.x + threadIdx.x;
    float4 v = reinterpret_cast<const float4*>(X)[i];
    reinterpret_cast<float4*>(g_xr)[i] = rna4(v);
}

// ===========================================================================
// W transpose + tf32 pre-round: src[R][C] -> dst[C][R] (dst in device code)
// which: 0 -> g_wt, 1 -> g_wtp
// ===========================================================================
__global__ void transpose_kernel(const float* __restrict__ src,
                                 int which, int R, int C)
{
    float* dst = which ? g_wtp : g_wt;
    __shared__ float tile[32][33];
    int bx = blockIdx.x * 32, by = blockIdx.y * 32;
#pragma unroll
    for (int i = 0; i < 32; i += 8)
        tile[threadIdx.y + i][threadIdx.x] =
            src[(size_t)(by + threadIdx.y + i) * C + bx + threadIdx.x];
    __syncthreads();
#pragma unroll
    for (int i = 0; i < 32; i += 8)
        dst[(size_t)(bx + threadIdx.y + i) * R + by + threadIdx.x] =
            rnaf(tile[threadIdx.x][threadIdx.y + i]);
}

// ===========================================================================
// tf32x1 mma GEMM, cp.async double-buffered. A and B BOTH pre-rounded in
// gmem -> mainloop is pure LDS + MMA (zero cvt/sub).
// C[128,128] tile = A[128,512] @ Bt[128,512]^T, both K-major ld=512.
// K-stage 32, SMEM stride 36; 256 threads = 8 warps (2m x 4n);
// warp tile 64m x 32n; acc[4][4][4]. SMEM 73728 B -> 2 CTAs/SM.
// (structure verified R13; only the lo-pass and cvt deleted)
// ===========================================================================
#define GK_STR 36
#define G_BUF  (128 * GK_STR)
#define G_SMEM_BYTES (4 * G_BUF * 4)           /* 73728 */

#define G_ISSUE_STAGE(kofs, bufb)                                               \
    do {                                                                        \
        _Pragma("unroll")                                                       \
        for (int i = 0; i < 4; i++) {                                           \
            int idx = i * 256 + t;                                              \
            int row = idx >> 3, c4 = (idx & 7) * 4;                             \
            CP_ASYNC16(sbase + (uint32_t)((bufb) * G_BUF + row * GK_STR + c4) * 4u, \
                       Abase + (size_t)row * 512 + (kofs) + c4);                \
            CP_ASYNC16(sbase + (uint32_t)(2 * G_BUF + (bufb) * G_BUF + row * GK_STR + c4) * 4u, \
                       Bbase + (size_t)row * 512 + (kofs) + c4);                \
        }                                                                       \
        CP_COMMIT();                                                            \
    } while (0)

#define MMA_GEMM_BODY(APTR, BTPTR)                                              \
    extern __shared__ float gsm[];                                              \
    const int t    = threadIdx.x;                                               \
    const int warp = t >> 5, lane = t & 31;                                     \
    const int wm   = warp >> 2, wn = warp & 3;                                  \
    const int lg   = lane >> 2, lq = lane & 3;                                  \
    const int row0 = blockIdx.y * 128, col0 = blockIdx.x * 128;                 \
    const float* Abase = (APTR) + (size_t)row0 * 512;                           \
    const float* Bbase = (BTPTR) + (size_t)col0 * 512;                          \
    const uint32_t sbase = smem_u32(gsm);                                       \
    float acc[4][4][4];                                                         \
    _Pragma("unroll") for (int i = 0; i < 4; i++)                               \
        _Pragma("unroll") for (int j = 0; j < 4; j++)                           \
            _Pragma("unroll") for (int c = 0; c < 4; c++) acc[i][j][c] = 0.f;   \
    G_ISSUE_STAGE(0, 0);                                                        \
    int buf = 0;                                                                \
    for (int st = 0; st < 16; st++) {                                           \
        CP_WAIT0();                                                             \
        __syncthreads();                                                        \
        if (st < 15) G_ISSUE_STAGE((st + 1) * 32, buf ^ 1);                     \
        const float* sA = gsm + buf * G_BUF;                                    \
        const float* sB = gsm + 2 * G_BUF + buf * G_BUF;                        \
        _Pragma("unroll")                                                       \
        for (int ks = 0; ks < 4; ks++) {                                        \
            const int k0 = ks * 8;                                              \
            uint32_t a[4][4], b[4][2];                                          \
            _Pragma("unroll")                                                   \
            for (int mf = 0; mf < 4; mf++) {                                    \
                int rA = wm * 64 + mf * 16 + lg;                                \
                a[mf][0] = __float_as_uint(sA[rA * GK_STR + k0 + lq]);          \
                a[mf][1] = __float_as_uint(sA[(rA + 8) * GK_STR + k0 + lq]);    \
                a[mf][2] = __float_as_uint(sA[rA * GK_STR + k0 + lq + 4]);      \
                a[mf][3] = __float_as_uint(sA[(rA + 8) * GK_STR + k0 + lq + 4]);\
            }                                                                   \
            _Pragma("unroll")                                                   \
            for (int nf = 0; nf < 4; nf++) {                                    \
                int nb = wn * 32 + nf * 8 + lg;                                 \
                b[nf][0] = __float_as_uint(sB[nb * GK_STR + k0 + lq]);          \
                b[nf][1] = __float_as_uint(sB[nb * GK_STR + k0 + lq + 4]);      \
            }                                                                   \
            _Pragma("unroll")                                                   \
            for (int mf = 0; mf < 4; mf++)                                      \
                _Pragma("unroll")                                               \
                for (int nf = 0; nf < 4; nf++)                                  \
                    mma_tf32(acc[mf][nf], a[mf], b[nf]);                        \
        }                                                                       \
        buf ^= 1;                                                               \
    }

// ---------------------------------------------------------------------------
// QKV GEMM (tf32x1): q -> g_q (log2-scaled, rounded), k/v -> d_out
// ---------------------------------------------------------------------------
__global__ __launch_bounds__(256, 2) void qkv_mma_kernel(float* __restrict__ dout)
{
    MMA_GEMM_BODY(g_xr, g_wt)

    const int s = col0 >> 9;                       // 0=q,1=k,2=v (block-uniform)
    const int h = ((col0 + wn * 32) >> 6) & 7;     // warp-uniform
#pragma unroll
    for (int mf = 0; mf < 4; mf++) {
        int m  = row0 + wm * 64 + mf * 16 + lg;
        int bb = m >> 11, n = m & 2047;
#pragma unroll
        for (int nf = 0; nf < 4; nf++) {
            int d = ((col0 + wn * 32 + nf * 8) & 63) + 2 * lq;
            size_t base0 = (((size_t)(bb * 8 + h)) * 2048 + n) * 64 + d;
            size_t base1 = base0 + 8 * 64;
            float2 v0 = make_float2(acc[mf][nf][0], acc[mf][nf][1]);
            float2 v1 = make_float2(acc[mf][nf][2], acc[mf][nf][3]);
            if (s == 0) {
                v0.x = rnaf(v0.x * QSCALE_); v0.y = rnaf(v0.y * QSCALE_);
                v1.x = rnaf(v1.x * QSCALE_); v1.y = rnaf(v1.y * QSCALE_);
                *reinterpret_cast<float2*>(&g_q[base0]) = v0;
                *reinterpret_cast<float2*>(&g_q[base1]) = v1;
            } else if (s == 1) {
                *reinterpret_cast<float2*>(dout + KOFF_ + base0) = v0;
                *reinterpret_cast<float2*>(dout + KOFF_ + base1) = v1;
            } else {
                *reinterpret_cast<float2*>(dout + VOFF_ + base0) = v0;
                *reinterpret_cast<float2*>(dout + VOFF_ + base1) = v1;
            }
        }
    }
}

// ---------------------------------------------------------------------------
// Proj GEMM (tf32x1): g_ao (pre-rounded) @ W_proj + bias -> d_out[0..]
// ---------------------------------------------------------------------------
__global__ __launch_bounds__(256, 2) void proj_mma_kernel(
    const float* __restrict__ bias, float* __restrict__ dout)
{
    MMA_GEMM_BODY(g_ao, g_wtp)

#pragma unroll
    for (int mf = 0; mf < 4; mf++) {
        int m = row0 + wm * 64 + mf * 16 + lg;
#pragma unroll
        for (int nf = 0; nf < 4; nf++) {
            int gcol = col0 + wn * 32 + nf * 8 + 2 * lq;
            float bx = bias[gcol], by = bias[gcol + 1];
            float* d0 = dout + (size_t)m * 512 + gcol;
            float* d1 = dout + (size_t)(m + 8) * 512 + gcol;
            *reinterpret_cast<float2*>(d0) =
                make_float2(acc[mf][nf][0] + bx, acc[mf][nf][1] + by);
            *reinterpret_cast<float2*>(d1) =
                make_float2(acc[mf][nf][2] + bx, acc[mf][nf][3] + by);
        }
    }
}

// ===========================================================================
// Flash attention: mma.sync tf32, QK^T = x1, PV = x1. (verified R11
// structure; deltas: Q arrives pre-rounded -> plain copy; g_ao store rounded)
// ===========================================================================
#define SQ_STR 68
#define SK_STR 68
#define SV_STR 72
#define SP_STR 132
#define AT_FLOATS (64*SQ_STR + 8704 + 128*SV_STR + 4*64)
#define AT_BYTES  (AT_FLOATS * 4)

__global__ __launch_bounds__(256, 2) void attn_mma_kernel(const float* __restrict__ dkv)
{
    extern __shared__ float sm[];
    float* sQ   = sm;                       // [64][68], pre-rounded
    float* sK   = sm + 64 * SQ_STR;         // [128][68], aliased by sP[64][132]
    float* sP   = sK;
    float* sV   = sK + 8704;                // [128][72]
    float* sRed = sV + 128 * SV_STR;        // [4][64]

    const int t    = threadIdx.x;
    const int warp = t >> 5, lane = t & 31;
    const int wm   = warp >> 2, wn = warp & 3;
    const int lg   = lane >> 2, lq = lane & 3;
    const int qt   = blockIdx.x, h = blockIdx.y, bb = blockIdx.z;

    const size_t bh = (size_t)(bb * 8 + h);
    const float* qb = g_q + (bh * 2048 + (size_t)qt * 64) * 64;
    const float* kb = dkv + KOFF_ + bh * 2048 * 64;
    const float* vb = dkv + VOFF_ + bh * 2048 * 64;

    // load Q tile [64][64] (already tf32-rounded by qkv epilogue)
#pragma unroll 4
    for (int i = t; i < 1024; i += 256) {
        int m = i >> 4, d4 = (i & 15) * 4;
        float4 v = *reinterpret_cast<const float4*>(qb + m * 64 + d4);
        *reinterpret_cast<float4*>(&sQ[m * SQ_STR + d4]) = v;
    }

    float o[2][2][4];
    float lsum[2][2];
#pragma unroll
    for (int mi = 0; mi < 2; mi++) {
        lsum[mi][0] = 0.f; lsum[mi][1] = 0.f;
#pragma unroll
        for (int nf = 0; nf < 2; nf++)
#pragma unroll
            for (int c = 0; c < 4; c++) o[mi][nf][c] = 0.f;
    }

    for (int j0 = 0; j0 < 2048; j0 += 128) {
        __syncthreads();
        // load K/V tiles, tf32-round at store
#pragma unroll 4
        for (int i = t; i < 2048; i += 256) {
            int j = i >> 4, d4 = (i & 15) * 4;
            float4 kv = *reinterpret_cast<const float4*>(kb + (size_t)(j0 + j) * 64 + d4);
            float4 vv = *reinterpret_cast<const float4*>(vb + (size_t)(j0 + j) * 64 + d4);
            *reinterpret_cast<float4*>(&sK[j * SK_STR + d4]) = rna4(kv);
            *reinterpret_cast<float4*>(&sV[j * SV_STR + d4]) = rna4(vv);
        }
        __syncthreads();

        float s[2][4][4];
#pragma unroll
        for (int mi = 0; mi < 2; mi++)
#pragma unroll
            for (int ni = 0; ni < 4; ni++)
#pragma unroll
                for (int c = 0; c < 4; c++) s[mi][ni][c] = 0.f;

#pragma unroll
        for (int ks = 0; ks < 8; ks++) {
            const int k0 = ks * 8;
            uint32_t a[2][4], b[4][2];
#pragma unroll
            for (int mi = 0; mi < 2; mi++) {
                int rA = wm * 32 + mi * 16 + lg;
                a[mi][0] = __float_as_uint(sQ[rA * SQ_STR + k0 + lq]);
                a[mi][1] = __float_as_uint(sQ[(rA + 8) * SQ_STR + k0 + lq]);
                a[mi][2] = __float_as_uint(sQ[rA * SQ_STR + k0 + lq + 4]);
                a[mi][3] = __float_as_uint(sQ[(rA + 8) * SQ_STR + k0 + lq + 4]);
            }
#pragma unroll
            for (int ni = 0; ni < 4; ni++) {
                int nb = wn * 32 + ni * 8 + lg;
                b[ni][0] = __float_as_uint(sK[nb * SK_STR + k0 + lq]);
                b[ni][1] = __float_as_uint(sK[nb * SK_STR + k0 + lq + 4]);
            }
#pragma unroll
            for (int mi = 0; mi < 2; mi++)
#pragma unroll
                for (int ni = 0; ni < 4; ni++)
                    mma_tf32(s[mi][ni], a[mi], b[ni]);
        }
        __syncthreads();

        // P = 2^S, tf32-rounded at store; lsum accumulates the ROUNDED P
#pragma unroll
        for (int mi = 0; mi < 2; mi++) {
            int row = wm * 32 + mi * 16 + lg;
#pragma unroll
            for (int ni = 0; ni < 4; ni++) {
                float p0 = rnaf(fexp2(s[mi][ni][0]));
                float p1 = rnaf(fexp2(s[mi][ni][1]));
                float p2 = rnaf(fexp2(s[mi][ni][2]));
                float p3 = rnaf(fexp2(s[mi][ni][3]));
                lsum[mi][0] += p0 + p1;
                lsum[mi][1] += p2 + p3;
                int col = wn * 32 + ni * 8 + 2 * lq;
                *reinterpret_cast<float2*>(&sP[row * SP_STR + col]) = make_float2(p0, p1);
                *reinterpret_cast<float2*>(&sP[(row + 8) * SP_STR + col]) = make_float2(p2, p3);
            }
        }
        __syncthreads();

#pragma unroll
        for (int kk = 0; kk < 16; kk++) {
            const int k0 = kk * 8;
            uint32_t phi[2][4], bv[2][2];
#pragma unroll
            for (int mi = 0; mi < 2; mi++) {
                int rA = wm * 32 + mi * 16 + lg;
                phi[mi][0] = __float_as_uint(sP[rA * SP_STR + k0 + lq]);
                phi[mi][1] = __float_as_uint(sP[(rA + 8) * SP_STR + k0 + lq]);
                phi[mi][2] = __float_as_uint(sP[rA * SP_STR + k0 + lq + 4]);
                phi[mi][3] = __float_as_uint(sP[(rA + 8) * SP_STR + k0 + lq + 4]);
            }
#pragma unroll
            for (int nf = 0; nf < 2; nf++) {
                int nb = wn * 16 + nf * 8 + lg;
                bv[nf][0] = __float_as_uint(sV[(k0 + lq) * SV_STR + nb]);
                bv[nf][1] = __float_as_uint(sV[(k0 + lq + 4) * SV_STR + nb]);
            }
#pragma unroll
            for (int mi = 0; mi < 2; mi++)
#pragma unroll
                for (int nf = 0; nf < 2; nf++)
                    mma_tf32(o[mi][nf], phi[mi], bv[nf]);
        }
    }

#pragma unroll
    for (int mi = 0; mi < 2; mi++)
#pragma unroll
        for (int hf = 0; hf < 2; hf++) {
            float v = lsum[mi][hf];
            v += __shfl_xor_sync(0xffffffffu, v, 1);
            v += __shfl_xor_sync(0xffffffffu, v, 2);
            lsum[mi][hf] = v;
            if (lq == 0)
                sRed[wn * 64 + wm * 32 + mi * 16 + lg + 8 * hf] = v;
        }
    __syncthreads();

#pragma unroll
    for (int mi = 0; mi < 2; mi++) {
        int row = wm * 32 + mi * 16 + lg;
        float l0 = sRed[0 * 64 + row] + sRed[1 * 64 + row] +
                   sRed[2 * 64 + row] + sRed[3 * 64 + row];
        float l1 = sRed[0 * 64 + row + 8] + sRed[1 * 64 + row + 8] +
                   sRed[2 * 64 + row + 8] + sRed[3 * 64 + row + 8];
        float inv0 = __fdividef(1.f, l0);
        float inv1 = __fdividef(1.f, l1);
        int n0 = qt * 64 + row;
#pragma unroll
        for (int nf = 0; nf < 2; nf++) {
            int col = h * 64 + wn * 16 + nf * 8 + 2 * lq;
            float* d0 = g_ao + ((size_t)bb * 2048 + n0) * 512 + col;
            float* d1 = g_ao + ((size_t)bb * 2048 + n0 + 8) * 512 + col;
            *reinterpret_cast<float2*>(d0) =
                make_float2(rnaf(o[mi][nf][0] * inv0), rnaf(o[mi][nf][1] * inv0));
            *reinterpret_cast<float2*>(d1) =
                make_float2(rnaf(o[mi][nf][2] * inv1), rnaf(o[mi][nf][3] * inv1));
        }
    }
}

// ===========================================================================
extern "C" void kernel_launch(void* const* d_in, const int* in_sizes, int n_in,
                              void* d_out, int out_size)
{
    const float* x     = (const float*)d_in[0];
    const float* wqkv  = (const float*)d_in[1];
    const float* wproj = (const float*)d_in[2];
    const float* bproj = (const float*)d_in[3];
    float* out = (float*)d_out;

    cudaFuncSetAttribute(attn_mma_kernel,
                         cudaFuncAttributeMaxDynamicSharedMemorySize, AT_BYTES);
    cudaFuncSetAttribute(qkv_mma_kernel,
                         cudaFuncAttributeMaxDynamicSharedMemorySize, G_SMEM_BYTES);
    cudaFuncSetAttribute(proj_mma_kernel,
                         cudaFuncAttributeMaxDynamicSharedMemorySize, G_SMEM_BYTES);

    round_x_kernel  <<<4096, 256>>>(x);                            // 4M floats / 4
    transpose_kernel<<<dim3(48, 16), dim3(32, 8)>>>(wqkv,  0, 512, 1536);
    transpose_kernel<<<dim3(16, 16), dim3(32, 8)>>>(wproj, 1, 512, 512);

    qkv_mma_kernel <<<dim3(12, 64), 256, G_SMEM_BYTES>>>(out);
    attn_mma_kernel<<<dim3(32, 8, 4), 256, AT_BYTES>>>(out);
    proj_mma_kernel<<<dim3(4, 64), 256, G_SMEM_BYTES>>>(bproj, out);
}

// round 15
// speedup vs baseline: 1.4048x; 1.0432x over previous
#include <cuda_runtime.h>
#include <cstdint>

#define BB_  4
#define NN_  2048
#define CC_  512
#define HH_  8
#define HD_  64
// q pre-scale: (1/sqrt(64)) * log2(e)  -> scores arrive in log2 domain
#define QSCALE_ 0.18033688011112042f

// d_out layout: [ out (B*N*C) | k (B*H*N*hd) | v (B*H*N*hd) ]
#define KOFF_ (4u * 2048u * 512u)
#define VOFF_ (8u * 2048u * 512u)

// scratch
__device__ float g_q  [BB_ * HH_ * NN_ * HD_];   // pre-scaled q, tf32-rounded
__device__ float g_ao [BB_ * NN_ * CC_];         // attention out, tf32-rounded
__device__ float g_xr [BB_ * NN_ * CC_];         // X, tf32-rounded
__device__ float g_wt [1536 * 512];              // W_qkv^T  [N][K], tf32-rounded
__device__ float g_wtp[512 * 512];               // W_proj^T [N][K], tf32-rounded

// ===========================================================================
// m16n8k8 tf32 mma (base ISA, works on plain sm_103 target)
// ===========================================================================
__device__ __forceinline__ void mma_tf32(float (&d)[4], const uint32_t (&a)[4],
                                         const uint32_t (&b)[2]) {
    asm volatile(
        "mma.sync.aligned.m16n8k8.row.col.f32.tf32.tf32.f32 "
        "{%0,%1,%2,%3}, {%4,%5,%6,%7}, {%8,%9}, {%0,%1,%2,%3};"
        : "+f"(d[0]), "+f"(d[1]), "+f"(d[2]), "+f"(d[3])
        : "r"(a[0]), "r"(a[1]), "r"(a[2]), "r"(a[3]), "r"(b[0]), "r"(b[1]));
}

__device__ __forceinline__ uint32_t tf32_rna(float x) {
    uint32_t r;
    asm("cvt.rna.tf32.f32 %0, %1;" : "=r"(r) : "f"(x));
    return r;
}
__device__ __forceinline__ float rnaf(float x) {
    return __uint_as_float(tf32_rna(x));
}
__device__ __forceinline__ float4 rna4(float4 v) {
    v.x = rnaf(v.x); v.y = rnaf(v.y); v.z = rnaf(v.z); v.w = rnaf(v.w);
    return v;
}
__device__ __forceinline__ uint32_t smem_u32(const void* p) {
    uint32_t a;
    asm("{ .reg .u64 t; cvta.to.shared.u64 t, %1; cvt.u32.u64 %0, t; }"
        : "=r"(a) : "l"(p));
    return a;
}

#define CP_ASYNC16(saddr, gptr) \
    asm volatile("cp.async.ca.shared.global [%0], [%1], 16;" \
        :: "r"(saddr), "l"(gptr) : "memory")
#define CP_COMMIT() \
    asm volatile("cp.async.commit_group;" ::: "memory")
#define CP_WAIT0() \
    asm volatile("cp.async.wait_group 0;" ::: "memory")

// fast 2^t on fma/alu pipes only (no MUFU). t >= -100 clamped; |err| ~ 3e-6.
__device__ __forceinline__ float fexp2(float t) {
    t = fmaxf(t, -100.f);
    float z = t + 12582912.f;
    int   n = __float_as_int(z) - 0x4B400000;
    float f = t - (z - 12582912.f);
    float p =        1.3333558e-3f;
    p = fmaf(p, f, 9.6181291e-3f);
    p = fmaf(p, f, 5.5504109e-2f);
    p = fmaf(p, f, 2.4022651e-1f);
    p = fmaf(p, f, 6.9314718e-1f);
    p = fmaf(p, f, 1.0f);
    return __int_as_float(__float_as_int(p) + (n << 23));
}

// ===========================================================================
// round_x: g_xr = tf32_rna(X)  (grid-stride float4)
// ===========================================================================
__global__ void round_x_kernel(const float* __restrict__ X)
{
    int i = blockIdx.x * blockDim.x + threadIdx.x;
    float4 v = reinterpret_cast<const float4*>(X)[i];
    reinterpret_cast<float4*>(g_xr)[i] = rna4(v);
}

// ===========================================================================
// W transpose + tf32 pre-round: src[R][C] -> dst[C][R] (dst in device code)
// which: 0 -> g_wt, 1 -> g_wtp
// ===========================================================================
__global__ void transpose_kernel(const float* __restrict__ src,
                                 int which, int R, int C)
{
    float* dst = which ? g_wtp : g_wt;
    __shared__ float tile[32][33];
    int bx = blockIdx.x * 32, by = blockIdx.y * 32;
#pragma unroll
    for (int i = 0; i < 32; i += 8)
        tile[threadIdx.y + i][threadIdx.x] =
            src[(size_t)(by + threadIdx.y + i) * C + bx + threadIdx.x];
    __syncthreads();
#pragma unroll
    for (int i = 0; i < 32; i += 8)
        dst[(size_t)(bx + threadIdx.y + i) * R + by + threadIdx.x] =
            rnaf(tile[threadIdx.x][threadIdx.y + i]);
}

// ===========================================================================
// tf32x1 mma GEMM, cp.async double-buffered (verified R14 — byte-identical)
// ===========================================================================
#define GK_STR 36
#define G_BUF  (128 * GK_STR)
#define G_SMEM_BYTES (4 * G_BUF * 4)           /* 73728 */

#define G_ISSUE_STAGE(kofs, bufb)                                               \
    do {                                                                        \
        _Pragma("unroll")                                                       \
        for (int i = 0; i < 4; i++) {                                           \
            int idx = i * 256 + t;                                              \
            int row = idx >> 3, c4 = (idx & 7) * 4;                             \
            CP_ASYNC16(sbase + (uint32_t)((bufb) * G_BUF + row * GK_STR + c4) * 4u, \
                       Abase + (size_t)row * 512 + (kofs) + c4);                \
            CP_ASYNC16(sbase + (uint32_t)(2 * G_BUF + (bufb) * G_BUF + row * GK_STR + c4) * 4u, \
                       Bbase + (size_t)row * 512 + (kofs) + c4);                \
        }                                                                       \
        CP_COMMIT();                                                            \
    } while (0)

#define MMA_GEMM_BODY(APTR, BTPTR)                                              \
    extern __shared__ float gsm[];                                              \
    const int t    = threadIdx.x;                                               \
    const int warp = t >> 5, lane = t & 31;                                     \
    const int wm   = warp >> 2, wn = warp & 3;                                  \
    const int lg   = lane >> 2, lq = lane & 3;                                  \
    const int row0 = blockIdx.y * 128, col0 = blockIdx.x * 128;                 \
    const float* Abase = (APTR) + (size_t)row0 * 512;                           \
    const float* Bbase = (BTPTR) + (size_t)col0 * 512;                          \
    const uint32_t sbase = smem_u32(gsm);                                       \
    float acc[4][4][4];                                                         \
    _Pragma("unroll") for (int i = 0; i < 4; i++)                               \
        _Pragma("unroll") for (int j = 0; j < 4; j++)                           \
            _Pragma("unroll") for (int c = 0; c < 4; c++) acc[i][j][c] = 0.f;   \
    G_ISSUE_STAGE(0, 0);                                                        \
    int buf = 0;                                                                \
    for (int st = 0; st < 16; st++) {                                           \
        CP_WAIT0();                                                             \
        __syncthreads();                                                        \
        if (st < 15) G_ISSUE_STAGE((st + 1) * 32, buf ^ 1);                     \
        const float* sA = gsm + buf * G_BUF;                                    \
        const float* sB = gsm + 2 * G_BUF + buf * G_BUF;                        \
        _Pragma("unroll")                                                       \
        for (int ks = 0; ks < 4; ks++) {                                        \
            const int k0 = ks * 8;                                              \
            uint32_t a[4][4], b[4][2];                                          \
            _Pragma("unroll")                                                   \
            for (int mf = 0; mf < 4; mf++) {                                    \
                int rA = wm * 64 + mf * 16 + lg;                                \
                a[mf][0] = __float_as_uint(sA[rA * GK_STR + k0 + lq]);          \
                a[mf][1] = __float_as_uint(sA[(rA + 8) * GK_STR + k0 + lq]);    \
                a[mf][2] = __float_as_uint(sA[rA * GK_STR + k0 + lq + 4]);      \
                a[mf][3] = __float_as_uint(sA[(rA + 8) * GK_STR + k0 + lq + 4]);\
            }                                                                   \
            _Pragma("unroll")                                                   \
            for (int nf = 0; nf < 4; nf++) {                                    \
                int nb = wn * 32 + nf * 8 + lg;                                 \
                b[nf][0] = __float_as_uint(sB[nb * GK_STR + k0 + lq]);          \
                b[nf][1] = __float_as_uint(sB[nb * GK_STR + k0 + lq + 4]);      \
            }                                                                   \
            _Pragma("unroll")                                                   \
            for (int mf = 0; mf < 4; mf++)                                      \
                _Pragma("unroll")                                               \
                for (int nf = 0; nf < 4; nf++)                                  \
                    mma_tf32(acc[mf][nf], a[mf], b[nf]);                        \
        }                                                                       \
        buf ^= 1;                                                               \
    }

// ---------------------------------------------------------------------------
// QKV GEMM (tf32x1): q -> g_q (log2-scaled, rounded), k/v -> d_out
// ---------------------------------------------------------------------------
__global__ __launch_bounds__(256, 2) void qkv_mma_kernel(float* __restrict__ dout)
{
    MMA_GEMM_BODY(g_xr, g_wt)

    const int s = col0 >> 9;                       // 0=q,1=k,2=v (block-uniform)
    const int h = ((col0 + wn * 32) >> 6) & 7;     // warp-uniform
#pragma unroll
    for (int mf = 0; mf < 4; mf++) {
        int m  = row0 + wm * 64 + mf * 16 + lg;
        int bb = m >> 11, n = m & 2047;
#pragma unroll
        for (int nf = 0; nf < 4; nf++) {
            int d = ((col0 + wn * 32 + nf * 8) & 63) + 2 * lq;
            size_t base0 = (((size_t)(bb * 8 + h)) * 2048 + n) * 64 + d;
            size_t base1 = base0 + 8 * 64;
            float2 v0 = make_float2(acc[mf][nf][0], acc[mf][nf][1]);
            float2 v1 = make_float2(acc[mf][nf][2], acc[mf][nf][3]);
            if (s == 0) {
                v0.x = rnaf(v0.x * QSCALE_); v0.y = rnaf(v0.y * QSCALE_);
                v1.x = rnaf(v1.x * QSCALE_); v1.y = rnaf(v1.y * QSCALE_);
                *reinterpret_cast<float2*>(&g_q[base0]) = v0;
                *reinterpret_cast<float2*>(&g_q[base1]) = v1;
            } else if (s == 1) {
                *reinterpret_cast<float2*>(dout + KOFF_ + base0) = v0;
                *reinterpret_cast<float2*>(dout + KOFF_ + base1) = v1;
            } else {
                *reinterpret_cast<float2*>(dout + VOFF_ + base0) = v0;
                *reinterpret_cast<float2*>(dout + VOFF_ + base1) = v1;
            }
        }
    }
}

// ---------------------------------------------------------------------------
// Proj GEMM (tf32x1): g_ao (pre-rounded) @ W_proj + bias -> d_out[0..]
// ---------------------------------------------------------------------------
__global__ __launch_bounds__(256, 2) void proj_mma_kernel(
    const float* __restrict__ bias, float* __restrict__ dout)
{
    MMA_GEMM_BODY(g_ao, g_wtp)

#pragma unroll
    for (int mf = 0; mf < 4; mf++) {
        int m = row0 + wm * 64 + mf * 16 + lg;
#pragma unroll
        for (int nf = 0; nf < 4; nf++) {
            int gcol = col0 + wn * 32 + nf * 8 + 2 * lq;
            float bx = bias[gcol], by = bias[gcol + 1];
            float* d0 = dout + (size_t)m * 512 + gcol;
            float* d1 = dout + (size_t)(m + 8) * 512 + gcol;
            *reinterpret_cast<float2*>(d0) =
                make_float2(acc[mf][nf][0] + bx, acc[mf][nf][1] + by);
            *reinterpret_cast<float2*>(d1) =
                make_float2(acc[mf][nf][2] + bx, acc[mf][nf][3] + by);
        }
    }
}

// ===========================================================================
// Flash attention: mma.sync tf32, QK^T = x1, PV = x1 with REGISTER-RESIDENT P.
// Each warp's P block (32q x 32j, accumulator layout) is converted to mma
// A-fragments via quad-local shfl + parity select and multiplied against V
// over its own j-chunk -> partial O[32q][64d] in registers. Partials from the
// 4 n-warps are summed once at block end in SMEM. No P SMEM round-trip; only
// 2 syncs per KV tile.
// SMEM: sQ[64][68] | sK[128][68] | sV[128][72] | sRed[4][64] | linv[64]
//       (22656 floats = 90624 B, 2 CTAs/SM; first 16384 floats reused for
//        the one-time partial-O reduction after the tile loop)
// ===========================================================================
#define SQ_STR 68
#define SK_STR 68
#define SV_STR 72
#define AT_FLOATS (64*SQ_STR + 128*SK_STR + 128*SV_STR + 256 + 64)
#define AT_BYTES  (AT_FLOATS * 4)

__global__ __launch_bounds__(256, 2) void attn_mma_kernel(const float* __restrict__ dkv)
{
    extern __shared__ float sm[];
    float* sQ   = sm;                              // [64][68], pre-rounded
    float* sK   = sm + 64 * SQ_STR;                // [128][68]
    float* sV   = sK + 128 * SK_STR;               // [128][72]
    float* sRed = sV + 128 * SV_STR;               // [4][64]
    float* sLinv = sRed + 256;                     // [64]

    const int t    = threadIdx.x;
    const int warp = t >> 5, lane = t & 31;
    const int wm   = warp >> 2, wn = warp & 3;
    const int lg   = lane >> 2, lq = lane & 3;
    const int qt   = blockIdx.x, h = blockIdx.y, bb = blockIdx.z;

    const int src0 = (lane & ~3) | (lq >> 1);      // quad-local shfl sources
    const int src1 = src0 + 2;
    const bool odd = (lq & 1);

    const size_t bh = (size_t)(bb * 8 + h);
    const float* qb = g_q + (bh * 2048 + (size_t)qt * 64) * 64;
    const float* kb = dkv + KOFF_ + bh * 2048 * 64;
    const float* vb = dkv + VOFF_ + bh * 2048 * 64;

    // load Q tile [64][64] (already tf32-rounded by qkv epilogue)
#pragma unroll 4
    for (int i = t; i < 1024; i += 256) {
        int m = i >> 4, d4 = (i & 15) * 4;
        float4 v = *reinterpret_cast<const float4*>(qb + m * 64 + d4);
        *reinterpret_cast<float4*>(&sQ[m * SQ_STR + d4]) = v;
    }

    float o[2][8][4];                 // partial O: rows wm*32+mi*16+{lg,lg+8},
    float lsum[2][2];                 //            cols nd*8+{2lq,2lq+1}
#pragma unroll
    for (int mi = 0; mi < 2; mi++) {
        lsum[mi][0] = 0.f; lsum[mi][1] = 0.f;
#pragma unroll
        for (int nd = 0; nd < 8; nd++)
#pragma unroll
            for (int c = 0; c < 4; c++) o[mi][nd][c] = 0.f;
    }

    for (int j0 = 0; j0 < 2048; j0 += 128) {
        __syncthreads();              // prev tile's QK^T/PV done reading sK/sV
        // load K/V tiles, tf32-round at store
#pragma unroll 4
        for (int i = t; i < 2048; i += 256) {
            int j = i >> 4, d4 = (i & 15) * 4;
            float4 kv = *reinterpret_cast<const float4*>(kb + (size_t)(j0 + j) * 64 + d4);
            float4 vv = *reinterpret_cast<const float4*>(vb + (size_t)(j0 + j) * 64 + d4);
            *reinterpret_cast<float4*>(&sK[j * SK_STR + d4]) = rna4(kv);
            *reinterpret_cast<float4*>(&sV[j * SV_STR + d4]) = rna4(vv);
        }
        __syncthreads();

        // ---- S = Q K^T (x1) ----
        float s[2][4][4];
#pragma unroll
        for (int mi = 0; mi < 2; mi++)
#pragma unroll
            for (int ni = 0; ni < 4; ni++)
#pragma unroll
                for (int c = 0; c < 4; c++) s[mi][ni][c] = 0.f;

#pragma unroll
        for (int ks = 0; ks < 8; ks++) {
            const int k0 = ks * 8;
            uint32_t a[2][4], b[4][2];
#pragma unroll
            for (int mi = 0; mi < 2; mi++) {
                int rA = wm * 32 + mi * 16 + lg;
                a[mi][0] = __float_as_uint(sQ[rA * SQ_STR + k0 + lq]);
                a[mi][1] = __float_as_uint(sQ[(rA + 8) * SQ_STR + k0 + lq]);
                a[mi][2] = __float_as_uint(sQ[rA * SQ_STR + k0 + lq + 4]);
                a[mi][3] = __float_as_uint(sQ[(rA + 8) * SQ_STR + k0 + lq + 4]);
            }
#pragma unroll
            for (int ni = 0; ni < 4; ni++) {
                int nb = wn * 32 + ni * 8 + lg;
                b[ni][0] = __float_as_uint(sK[nb * SK_STR + k0 + lq]);
                b[ni][1] = __float_as_uint(sK[nb * SK_STR + k0 + lq + 4]);
            }
#pragma unroll
            for (int mi = 0; mi < 2; mi++)
#pragma unroll
                for (int ni = 0; ni < 4; ni++)
                    mma_tf32(s[mi][ni], a[mi], b[ni]);
        }

        // ---- P = 2^S in registers (tf32-rounded); accumulate lsum ----
#pragma unroll
        for (int mi = 0; mi < 2; mi++)
#pragma unroll
            for (int ni = 0; ni < 4; ni++) {
                float p0 = rnaf(fexp2(s[mi][ni][0]));
                float p1 = rnaf(fexp2(s[mi][ni][1]));
                float p2 = rnaf(fexp2(s[mi][ni][2]));
                float p3 = rnaf(fexp2(s[mi][ni][3]));
                lsum[mi][0] += p0 + p1;
                lsum[mi][1] += p2 + p3;
                s[mi][ni][0] = p0; s[mi][ni][1] = p1;
                s[mi][ni][2] = p2; s[mi][ni][3] = p3;
            }

        // ---- O_partial += P V over this warp's j-chunk (k = 32) ----
#pragma unroll
        for (int kk = 0; kk < 4; kk++) {
            uint32_t afr[2][4];
#pragma unroll
            for (int mi = 0; mi < 2; mi++) {
                float q00 = __shfl_sync(0xffffffffu, s[mi][kk][0], src0);
                float q01 = __shfl_sync(0xffffffffu, s[mi][kk][1], src0);
                float q20 = __shfl_sync(0xffffffffu, s[mi][kk][2], src0);
                float q21 = __shfl_sync(0xffffffffu, s[mi][kk][3], src0);
                float r00 = __shfl_sync(0xffffffffu, s[mi][kk][0], src1);
                float r01 = __shfl_sync(0xffffffffu, s[mi][kk][1], src1);
                float r20 = __shfl_sync(0xffffffffu, s[mi][kk][2], src1);
                float r21 = __shfl_sync(0xffffffffu, s[mi][kk][3], src1);
                afr[mi][0] = __float_as_uint(odd ? q01 : q00);
                afr[mi][1] = __float_as_uint(odd ? q21 : q20);
                afr[mi][2] = __float_as_uint(odd ? r01 : r00);
                afr[mi][3] = __float_as_uint(odd ? r21 : r20);
            }
            const int jrow = wn * 32 + kk * 8;
#pragma unroll
            for (int nd = 0; nd < 8; nd++) {
                uint32_t b[2];
                b[0] = __float_as_uint(sV[(jrow + lq) * SV_STR + nd * 8 + lg]);
                b[1] = __float_as_uint(sV[(jrow + lq + 4) * SV_STR + nd * 8 + lg]);
                mma_tf32(o[0][nd], afr[0], b);
                mma_tf32(o[1][nd], afr[1], b);
            }
        }
    }

    // ---- lsum reduction across n-warps (as verified) ----
#pragma unroll
    for (int mi = 0; mi < 2; mi++)
#pragma unroll
        for (int hf = 0; hf < 2; hf++) {
            float v = lsum[mi][hf];
            v += __shfl_xor_sync(0xffffffffu, v, 1);
            v += __shfl_xor_sync(0xffffffffu, v, 2);
            lsum[mi][hf] = v;
        }

    __syncthreads();                 // all PV reads of sV complete

    // ---- store partial O to SMEM [wn][64 rows][64 cols] (reuses sQ/sK/sV) ----
#pragma unroll
    for (int mi = 0; mi < 2; mi++) {
        int row = wm * 32 + mi * 16 + lg;
        int base = wn * 4096 + row * 64 + 2 * lq;
#pragma unroll
        for (int nd = 0; nd < 8; nd++) {
            *reinterpret_cast<float2*>(&sm[base + nd * 8]) =
                make_float2(o[mi][nd][0], o[mi][nd][1]);
            *reinterpret_cast<float2*>(&sm[base + 512 + nd * 8]) =
                make_float2(o[mi][nd][2], o[mi][nd][3]);
        }
    }
    // lsum -> sRed (disjoint from partial region)
    if (lq == 0) {
#pragma unroll
        for (int mi = 0; mi < 2; mi++) {
            sRed[wn * 64 + wm * 32 + mi * 16 + lg]     = lsum[mi][0];
            sRed[wn * 64 + wm * 32 + mi * 16 + lg + 8] = lsum[mi][1];
        }
    }
    __syncthreads();

    if (t < 64)
        sLinv[t] = __fdividef(1.f, sRed[t] + sRed[64 + t] + sRed[128 + t] + sRed[192 + t]);
    __syncthreads();

    // ---- reduce 4 partials, normalize, round, write g_ao ----
    for (int i2 = t; i2 < 2048; i2 += 256) {
        int row = i2 >> 5, c2 = (i2 & 31) * 2;
        float2 a0 = *reinterpret_cast<float2*>(&sm[0 * 4096 + row * 64 + c2]);
        float2 a1 = *reinterpret_cast<float2*>(&sm[1 * 4096 + row * 64 + c2]);
        float2 a2 = *reinterpret_cast<float2*>(&sm[2 * 4096 + row * 64 + c2]);
        float2 a3 = *reinterpret_cast<float2*>(&sm[3 * 4096 + row * 64 + c2]);
        float li = sLinv[row];
        float vx = rnaf((a0.x + a1.x + a2.x + a3.x) * li);
        float vy = rnaf((a0.y + a1.y + a2.y + a3.y) * li);
        int n = qt * 64 + row;
        *reinterpret_cast<float2*>(g_ao + ((size_t)bb * 2048 + n) * 512 + h * 64 + c2) =
            make_float2(vx, vy);
    }
}

// ===========================================================================
extern "C" void kernel_launch(void* const* d_in, const int* in_sizes, int n_in,
                              void* d_out, int out_size)
{
    const float* x     = (const float*)d_in[0];
    const float* wqkv  = (const float*)d_in[1];
    const float* wproj = (const float*)d_in[2];
    const float* bproj = (const float*)d_in[3];
    float* out = (float*)d_out;

    cudaFuncSetAttribute(attn_mma_kernel,
                         cudaFuncAttributeMaxDynamicSharedMemorySize, AT_BYTES);
    cudaFuncSetAttribute(qkv_mma_kernel,
                         cudaFuncAttributeMaxDynamicSharedMemorySize, G_SMEM_BYTES);
    cudaFuncSetAttribute(proj_mma_kernel,
                         cudaFuncAttributeMaxDynamicSharedMemorySize, G_SMEM_BYTES);

    round_x_kernel  <<<4096, 256>>>(x);
    transpose_kernel<<<dim3(48, 16), dim3(32, 8)>>>(wqkv,  0, 512, 1536);
    transpose_kernel<<<dim3(16, 16), dim3(32, 8)>>>(wproj, 1, 512, 512);

    qkv_mma_kernel <<<dim3(12, 64), 256, G_SMEM_BYTES>>>(out);
    attn_mma_kernel<<<dim3(32, 8, 4), 256, AT_BYTES>>>(out);
    proj_mma_kernel<<<dim3(4, 64), 256, G_SMEM_BYTES>>>(bproj, out);
}

// round 16
// speedup vs baseline: 1.4093x; 1.0032x over previous
#include <cuda_runtime.h>
#include <cstdint>

#define BB_  4
#define NN_  2048
#define CC_  512
#define HH_  8
#define HD_  64
// q pre-scale: (1/sqrt(64)) * log2(e)  -> scores arrive in log2 domain
#define QSCALE_ 0.18033688011112042f

// d_out layout: [ out (B*N*C) | k (B*H*N*hd) | v (B*H*N*hd) ]
#define KOFF_ (4u * 2048u * 512u)
#define VOFF_ (8u * 2048u * 512u)

// scratch
__device__ float g_q  [BB_ * HH_ * NN_ * HD_];   // pre-scaled q, tf32-rounded
__device__ float g_kr [BB_ * HH_ * NN_ * HD_];   // k, tf32-rounded
__device__ float g_vr [BB_ * HH_ * NN_ * HD_];   // v, tf32-rounded
__device__ float g_ao [BB_ * NN_ * CC_];         // attention out, tf32-rounded
__device__ float g_xr [BB_ * NN_ * CC_];         // X, tf32-rounded
__device__ float g_wt [1536 * 512];              // W_qkv^T  [N][K], tf32-rounded
__device__ float g_wtp[512 * 512];               // W_proj^T [N][K], tf32-rounded

// ===========================================================================
// m16n8k8 tf32 mma (base ISA, works on plain sm_103 target)
// ===========================================================================
__device__ __forceinline__ void mma_tf32(float (&d)[4], const uint32_t (&a)[4],
                                         const uint32_t (&b)[2]) {
    asm volatile(
        "mma.sync.aligned.m16n8k8.row.col.f32.tf32.tf32.f32 "
        "{%0,%1,%2,%3}, {%4,%5,%6,%7}, {%8,%9}, {%0,%1,%2,%3};"
        : "+f"(d[0]), "+f"(d[1]), "+f"(d[2]), "+f"(d[3])
        : "r"(a[0]), "r"(a[1]), "r"(a[2]), "r"(a[3]), "r"(b[0]), "r"(b[1]));
}

__device__ __forceinline__ uint32_t tf32_rna(float x) {
    uint32_t r;
    asm("cvt.rna.tf32.f32 %0, %1;" : "=r"(r) : "f"(x));
    return r;
}
__device__ __forceinline__ float rnaf(float x) {
    return __uint_as_float(tf32_rna(x));
}
__device__ __forceinline__ float4 rna4(float4 v) {
    v.x = rnaf(v.x); v.y = rnaf(v.y); v.z = rnaf(v.z); v.w = rnaf(v.w);
    return v;
}
__device__ __forceinline__ uint32_t smem_u32(const void* p) {
    uint32_t a;
    asm("{ .reg .u64 t; cvta.to.shared.u64 t, %1; cvt.u32.u64 %0, t; }"
        : "=r"(a) : "l"(p));
    return a;
}

#define CP_ASYNC16(saddr, gptr) \
    asm volatile("cp.async.ca.shared.global [%0], [%1], 16;" \
        :: "r"(saddr), "l"(gptr) : "memory")
#define CP_COMMIT() \
    asm volatile("cp.async.commit_group;" ::: "memory")
#define CP_WAIT0() \
    asm volatile("cp.async.wait_group 0;" ::: "memory")

// fast 2^t on fma/alu pipes only (no MUFU). t >= -100 clamped; |err| ~ 3e-6.
__device__ __forceinline__ float fexp2(float t) {
    t = fmaxf(t, -100.f);
    float z = t + 12582912.f;
    int   n = __float_as_int(z) - 0x4B400000;
    float f = t - (z - 12582912.f);
    float p =        1.3333558e-3f;
    p = fmaf(p, f, 9.6181291e-3f);
    p = fmaf(p, f, 5.5504109e-2f);
    p = fmaf(p, f, 2.4022651e-1f);
    p = fmaf(p, f, 6.9314718e-1f);
    p = fmaf(p, f, 1.0f);
    return __int_as_float(__float_as_int(p) + (n << 23));
}

// ===========================================================================
// round_x: g_xr = tf32_rna(X)  (grid-stride float4)
// ===========================================================================
__global__ void round_x_kernel(const float* __restrict__ X)
{
    int i = blockIdx.x * blockDim.x + threadIdx.x;
    float4 v = reinterpret_cast<const float4*>(X)[i];
    reinterpret_cast<float4*>(g_xr)[i] = rna4(v);
}

// ===========================================================================
// W transpose + tf32 pre-round: src[R][C] -> dst[C][R] (dst in device code)
// which: 0 -> g_wt, 1 -> g_wtp
// ===========================================================================
__global__ void transpose_kernel(const float* __restrict__ src,
                                 int which, int R, int C)
{
    float* dst = which ? g_wtp : g_wt;
    __shared__ float tile[32][33];
    int bx = blockIdx.x * 32, by = blockIdx.y * 32;
#pragma unroll
    for (int i = 0; i < 32; i += 8)
        tile[threadIdx.y + i][threadIdx.x] =
            src[(size_t)(by + threadIdx.y + i) * C + bx + threadIdx.x];
    __syncthreads();
#pragma unroll
    for (int i = 0; i < 32; i += 8)
        dst[(size_t)(bx + threadIdx.y + i) * R + by + threadIdx.x] =
            rnaf(tile[threadIdx.x][threadIdx.y + i]);
}

// ===========================================================================
// tf32x1 mma GEMM, cp.async double-buffered (verified R14 — byte-identical)
// ===========================================================================
#define GK_STR 36
#define G_BUF  (128 * GK_STR)
#define G_SMEM_BYTES (4 * G_BUF * 4)           /* 73728 */

#define G_ISSUE_STAGE(kofs, bufb)                                               \
    do {                                                                        \
        _Pragma("unroll")                                                       \
        for (int i = 0; i < 4; i++) {                                           \
            int idx = i * 256 + t;                                              \
            int row = idx >> 3, c4 = (idx & 7) * 4;                             \
            CP_ASYNC16(sbase + (uint32_t)((bufb) * G_BUF + row * GK_STR + c4) * 4u, \
                       Abase + (size_t)row * 512 + (kofs) + c4);                \
            CP_ASYNC16(sbase + (uint32_t)(2 * G_BUF + (bufb) * G_BUF + row * GK_STR + c4) * 4u, \
                       Bbase + (size_t)row * 512 + (kofs) + c4);                \
        }                                                                       \
        CP_COMMIT();                                                            \
    } while (0)

#define MMA_GEMM_BODY(APTR, BTPTR)                                              \
    extern __shared__ float gsm[];                                              \
    const int t    = threadIdx.x;                                               \
    const int warp = t >> 5, lane = t & 31;                                     \
    const int wm   = warp >> 2, wn = warp & 3;                                  \
    const int lg   = lane >> 2, lq = lane & 3;                                  \
    const int row0 = blockIdx.y * 128, col0 = blockIdx.x * 128;                 \
    const float* Abase = (APTR) + (size_t)row0 * 512;                           \
    const float* Bbase = (BTPTR) + (size_t)col0 * 512;                          \
    const uint32_t sbase = smem_u32(gsm);                                       \
    float acc[4][4][4];                                                         \
    _Pragma("unroll") for (int i = 0; i < 4; i++)                               \
        _Pragma("unroll") for (int j = 0; j < 4; j++)                           \
            _Pragma("unroll") for (int c = 0; c < 4; c++) acc[i][j][c] = 0.f;   \
    G_ISSUE_STAGE(0, 0);                                                        \
    int buf = 0;                                                                \
    for (int st = 0; st < 16; st++) {                                           \
        CP_WAIT0();                                                             \
        __syncthreads();                                                        \
        if (st < 15) G_ISSUE_STAGE((st + 1) * 32, buf ^ 1);                     \
        const float* sA = gsm + buf * G_BUF;                                    \
        const float* sB = gsm + 2 * G_BUF + buf * G_BUF;                        \
        _Pragma("unroll")                                                       \
        for (int ks = 0; ks < 4; ks++) {                                        \
            const int k0 = ks * 8;                                              \
            uint32_t a[4][4], b[4][2];                                          \
            _Pragma("unroll")                                                   \
            for (int mf = 0; mf < 4; mf++) {                                    \
                int rA = wm * 64 + mf * 16 + lg;                                \
                a[mf][0] = __float_as_uint(sA[rA * GK_STR + k0 + lq]);          \
                a[mf][1] = __float_as_uint(sA[(rA + 8) * GK_STR + k0 + lq]);    \
                a[mf][2] = __float_as_uint(sA[rA * GK_STR + k0 + lq + 4]);      \
                a[mf][3] = __float_as_uint(sA[(rA + 8) * GK_STR + k0 + lq + 4]);\
            }                                                                   \
            _Pragma("unroll")                                                   \
            for (int nf = 0; nf < 4; nf++) {                                    \
                int nb = wn * 32 + nf * 8 + lg;                                 \
                b[nf][0] = __float_as_uint(sB[nb * GK_STR + k0 + lq]);          \
                b[nf][1] = __float_as_uint(sB[nb * GK_STR + k0 + lq + 4]);      \
            }                                                                   \
            _Pragma("unroll")                                                   \
            for (int mf = 0; mf < 4; mf++)                                      \
                _Pragma("unroll")                                               \
                for (int nf = 0; nf < 4; nf++)                                  \
                    mma_tf32(acc[mf][nf], a[mf], b[nf]);                        \
        }                                                                       \
        buf ^= 1;                                                               \
    }

// ---------------------------------------------------------------------------
// QKV GEMM (tf32x1): q -> g_q (scaled+rounded), k/v -> d_out (full precision)
// AND rounded copies -> g_kr/g_vr (same values attention used to compute).
// ---------------------------------------------------------------------------
__global__ __launch_bounds__(256, 2) void qkv_mma_kernel(float* __restrict__ dout)
{
    MMA_GEMM_BODY(g_xr, g_wt)

    const int s = col0 >> 9;                       // 0=q,1=k,2=v (block-uniform)
    const int h = ((col0 + wn * 32) >> 6) & 7;     // warp-uniform
#pragma unroll
    for (int mf = 0; mf < 4; mf++) {
        int m  = row0 + wm * 64 + mf * 16 + lg;
        int bb = m >> 11, n = m & 2047;
#pragma unroll
        for (int nf = 0; nf < 4; nf++) {
            int d = ((col0 + wn * 32 + nf * 8) & 63) + 2 * lq;
            size_t base0 = (((size_t)(bb * 8 + h)) * 2048 + n) * 64 + d;
            size_t base1 = base0 + 8 * 64;
            float2 v0 = make_float2(acc[mf][nf][0], acc[mf][nf][1]);
            float2 v1 = make_float2(acc[mf][nf][2], acc[mf][nf][3]);
            if (s == 0) {
                v0.x = rnaf(v0.x * QSCALE_); v0.y = rnaf(v0.y * QSCALE_);
                v1.x = rnaf(v1.x * QSCALE_); v1.y = rnaf(v1.y * QSCALE_);
                *reinterpret_cast<float2*>(&g_q[base0]) = v0;
                *reinterpret_cast<float2*>(&g_q[base1]) = v1;
            } else if (s == 1) {
                *reinterpret_cast<float2*>(dout + KOFF_ + base0) = v0;
                *reinterpret_cast<float2*>(dout + KOFF_ + base1) = v1;
                *reinterpret_cast<float2*>(&g_kr[base0]) =
                    make_float2(rnaf(v0.x), rnaf(v0.y));
                *reinterpret_cast<float2*>(&g_kr[base1]) =
                    make_float2(rnaf(v1.x), rnaf(v1.y));
            } else {
                *reinterpret_cast<float2*>(dout + VOFF_ + base0) = v0;
                *reinterpret_cast<float2*>(dout + VOFF_ + base1) = v1;
                *reinterpret_cast<float2*>(&g_vr[base0]) =
                    make_float2(rnaf(v0.x), rnaf(v0.y));
                *reinterpret_cast<float2*>(&g_vr[base1]) =
                    make_float2(rnaf(v1.x), rnaf(v1.y));
            }
        }
    }
}

// ---------------------------------------------------------------------------
// Proj GEMM (tf32x1): g_ao (pre-rounded) @ W_proj + bias -> d_out[0..]
// ---------------------------------------------------------------------------
__global__ __launch_bounds__(256, 2) void proj_mma_kernel(
    const float* __restrict__ bias, float* __restrict__ dout)
{
    MMA_GEMM_BODY(g_ao, g_wtp)

#pragma unroll
    for (int mf = 0; mf < 4; mf++) {
        int m = row0 + wm * 64 + mf * 16 + lg;
#pragma unroll
        for (int nf = 0; nf < 4; nf++) {
            int gcol = col0 + wn * 32 + nf * 8 + 2 * lq;
            float bx = bias[gcol], by = bias[gcol + 1];
            float* d0 = dout + (size_t)m * 512 + gcol;
            float* d1 = dout + (size_t)(m + 8) * 512 + gcol;
            *reinterpret_cast<float2*>(d0) =
                make_float2(acc[mf][nf][0] + bx, acc[mf][nf][1] + by);
            *reinterpret_cast<float2*>(d1) =
                make_float2(acc[mf][nf][2] + bx, acc[mf][nf][3] + by);
        }
    }
}

// ===========================================================================
// Flash attention: register-P (verified R15 core) + cp.async pipelined K/V.
// K and V pre-rounded in gmem (g_kr/g_vr). Fixed buffers sKb/sVb (stride 76):
//   V(j) copy overlaps QK(j) compute; K(j+1) copy overlaps PV(j) compute.
// Bank check (stride 76 = 12 mod 32): K frag (12lg+lq) and V frag
// (12lq+8nd+lg) both hit 32 distinct banks.
// SMEM: sQ[64][68] | sKb[128][76] | sVb[128][76] | sRed[256] | linv[64]
//       = 24128 floats = 96512 B -> 2 CTAs/SM. Partial-O reduction reuses
//       the first 16384 floats after the tile loop.
// ===========================================================================
#define SQ_STR 68
#define KV_STR 76
#define KV_BUF (128 * KV_STR)
#define AT_SQF (64 * SQ_STR)
#define AT_FLOATS (AT_SQF + 2 * KV_BUF + 256 + 64)
#define AT_BYTES  (AT_FLOATS * 4)

#define AT_ISSUE(gptr, j0, bufofs)                                              \
    do {                                                                        \
        _Pragma("unroll")                                                       \
        for (int i = 0; i < 8; i++) {                                           \
            int idx = i * 256 + t;                                              \
            int row = idx >> 4, c4 = (idx & 15) * 4;                            \
            CP_ASYNC16(skv_base + (uint32_t)((bufofs) + row * KV_STR + c4) * 4u,\
                       (gptr) + (size_t)((j0) + row) * 64 + c4);                \
        }                                                                       \
        CP_COMMIT();                                                            \
    } while (0)

__global__ __launch_bounds__(256, 2) void attn_mma_kernel()
{
    extern __shared__ float sm[];
    float* sQ    = sm;                             // [64][68]
    float* sKb   = sm + AT_SQF;                    // [128][76]
    float* sVb   = sKb + KV_BUF;                   // [128][76]
    float* sRed  = sVb + KV_BUF;                   // [256]
    float* sLinv = sRed + 256;                     // [64]
    const uint32_t skv_base = smem_u32(sKb);

    const int t    = threadIdx.x;
    const int warp = t >> 5, lane = t & 31;
    const int wm   = warp >> 2, wn = warp & 3;
    const int lg   = lane >> 2, lq = lane & 3;
    const int qt   = blockIdx.x, h = blockIdx.y, bb = blockIdx.z;

    const int src0 = (lane & ~3) | (lq >> 1);
    const int src1 = src0 + 2;
    const bool odd = (lq & 1);

    const size_t bh = (size_t)(bb * 8 + h);
    const float* qb = g_q  + (bh * 2048 + (size_t)qt * 64) * 64;
    const float* kb = g_kr + bh * 2048 * 64;
    const float* vb = g_vr + bh * 2048 * 64;

    // preload K(0)
    AT_ISSUE(kb, 0, 0);

    // load Q tile [64][64] (pre-rounded)
#pragma unroll 4
    for (int i = t; i < 1024; i += 256) {
        int m = i >> 4, d4 = (i & 15) * 4;
        float4 v = *reinterpret_cast<const float4*>(qb + m * 64 + d4);
        *reinterpret_cast<float4*>(&sQ[m * SQ_STR + d4]) = v;
    }

    float o[2][8][4];
    float lsum[2][2];
#pragma unroll
    for (int mi = 0; mi < 2; mi++) {
        lsum[mi][0] = 0.f; lsum[mi][1] = 0.f;
#pragma unroll
        for (int nd = 0; nd < 8; nd++)
#pragma unroll
            for (int c = 0; c < 4; c++) o[mi][nd][c] = 0.f;
    }

    float s[2][4][4];

    for (int j = 0; j < 16; j++) {
        const int j0 = j * 128;

        // ---- K phase: K(j) ready; prev PV done reading sVb ----
        CP_WAIT0();
        __syncthreads();
        AT_ISSUE(vb, j0, KV_BUF);        // V(j) copies during QK(j)

#pragma unroll
        for (int mi = 0; mi < 2; mi++)
#pragma unroll
            for (int ni = 0; ni < 4; ni++)
#pragma unroll
                for (int c = 0; c < 4; c++) s[mi][ni][c] = 0.f;

#pragma unroll
        for (int ks = 0; ks < 8; ks++) {
            const int k0 = ks * 8;
            uint32_t a[2][4], b[4][2];
#pragma unroll
            for (int mi = 0; mi < 2; mi++) {
                int rA = wm * 32 + mi * 16 + lg;
                a[mi][0] = __float_as_uint(sQ[rA * SQ_STR + k0 + lq]);
                a[mi][1] = __float_as_uint(sQ[(rA + 8) * SQ_STR + k0 + lq]);
                a[mi][2] = __float_as_uint(sQ[rA * SQ_STR + k0 + lq + 4]);
                a[mi][3] = __float_as_uint(sQ[(rA + 8) * SQ_STR + k0 + lq + 4]);
            }
#pragma unroll
            for (int ni = 0; ni < 4; ni++) {
                int nb = wn * 32 + ni * 8 + lg;
                b[ni][0] = __float_as_uint(sKb[nb * KV_STR + k0 + lq]);
                b[ni][1] = __float_as_uint(sKb[nb * KV_STR + k0 + lq + 4]);
            }
#pragma unroll
            for (int mi = 0; mi < 2; mi++)
#pragma unroll
                for (int ni = 0; ni < 4; ni++)
                    mma_tf32(s[mi][ni], a[mi], b[ni]);
        }

        // P = 2^S in registers (tf32-rounded); accumulate lsum
#pragma unroll
        for (int mi = 0; mi < 2; mi++)
#pragma unroll
            for (int ni = 0; ni < 4; ni++) {
                float p0 = rnaf(fexp2(s[mi][ni][0]));
                float p1 = rnaf(fexp2(s[mi][ni][1]));
                float p2 = rnaf(fexp2(s[mi][ni][2]));
                float p3 = rnaf(fexp2(s[mi][ni][3]));
                lsum[mi][0] += p0 + p1;
                lsum[mi][1] += p2 + p3;
                s[mi][ni][0] = p0; s[mi][ni][1] = p1;
                s[mi][ni][2] = p2; s[mi][ni][3] = p3;
            }

        // ---- V phase: V(j) ready; QK done reading sKb ----
        CP_WAIT0();
        __syncthreads();
        if (j < 15) AT_ISSUE(kb, j0 + 128, 0);    // K(j+1) copies during PV(j)

#pragma unroll
        for (int kk = 0; kk < 4; kk++) {
            uint32_t afr[2][4];
#pragma unroll
            for (int mi = 0; mi < 2; mi++) {
                float q00 = __shfl_sync(0xffffffffu, s[mi][kk][0], src0);
                float q01 = __shfl_sync(0xffffffffu, s[mi][kk][1], src0);
                float q20 = __shfl_sync(0xffffffffu, s[mi][kk][2], src0);
                float q21 = __shfl_sync(0xffffffffu, s[mi][kk][3], src0);
                float r00 = __shfl_sync(0xffffffffu, s[mi][kk][0], src1);
                float r01 = __shfl_sync(0xffffffffu, s[mi][kk][1], src1);
                float r20 = __shfl_sync(0xffffffffu, s[mi][kk][2], src1);
                float r21 = __shfl_sync(0xffffffffu, s[mi][kk][3], src1);
                afr[mi][0] = __float_as_uint(odd ? q01 : q00);
                afr[mi][1] = __float_as_uint(odd ? q21 : q20);
                afr[mi][2] = __float_as_uint(odd ? r01 : r00);
                afr[mi][3] = __float_as_uint(odd ? r21 : r20);
            }
            const int jrow = wn * 32 + kk * 8;
#pragma unroll
            for (int nd = 0; nd < 8; nd++) {
                uint32_t b[2];
                b[0] = __float_as_uint(sVb[(jrow + lq) * KV_STR + nd * 8 + lg]);
                b[1] = __float_as_uint(sVb[(jrow + lq + 4) * KV_STR + nd * 8 + lg]);
                mma_tf32(o[0][nd], afr[0], b);
                mma_tf32(o[1][nd], afr[1], b);
            }
        }
    }

    // ---- lsum reduction across quads ----
#pragma unroll
    for (int mi = 0; mi < 2; mi++)
#pragma unroll
        for (int hf = 0; hf < 2; hf++) {
            float v = lsum[mi][hf];
            v += __shfl_xor_sync(0xffffffffu, v, 1);
            v += __shfl_xor_sync(0xffffffffu, v, 2);
            lsum[mi][hf] = v;
        }

    __syncthreads();                 // all PV reads of sVb complete

    // ---- store partial O to SMEM [wn][64 rows][64 cols] (reuses sQ/sKb/sVb) ----
#pragma unroll
    for (int mi = 0; mi < 2; mi++) {
        int row = wm * 32 + mi * 16 + lg;
        int base = wn * 4096 + row * 64 + 2 * lq;
#pragma unroll
        for (int nd = 0; nd < 8; nd++) {
            *reinterpret_cast<float2*>(&sm[base + nd * 8]) =
                make_float2(o[mi][nd][0], o[mi][nd][1]);
            *reinterpret_cast<float2*>(&sm[base + 512 + nd * 8]) =
                make_float2(o[mi][nd][2], o[mi][nd][3]);
        }
    }
    if (lq == 0) {
#pragma unroll
        for (int mi = 0; mi < 2; mi++) {
            sRed[wn * 64 + wm * 32 + mi * 16 + lg]     = lsum[mi][0];
            sRed[wn * 64 + wm * 32 + mi * 16 + lg + 8] = lsum[mi][1];
        }
    }
    __syncthreads();

    if (t < 64)
        sLinv[t] = __fdividef(1.f, sRed[t] + sRed[64 + t] + sRed[128 + t] + sRed[192 + t]);
    __syncthreads();

    // ---- reduce 4 partials, normalize, round, write g_ao ----
    for (int i2 = t; i2 < 2048; i2 += 256) {
        int row = i2 >> 5, c2 = (i2 & 31) * 2;
        float2 a0 = *reinterpret_cast<float2*>(&sm[0 * 4096 + row * 64 + c2]);
        float2 a1 = *reinterpret_cast<float2*>(&sm[1 * 4096 + row * 64 + c2]);
        float2 a2 = *reinterpret_cast<float2*>(&sm[2 * 4096 + row * 64 + c2]);
        float2 a3 = *reinterpret_cast<float2*>(&sm[3 * 4096 + row * 64 + c2]);
        float li = sLinv[row];
        float vx = rnaf((a0.x + a1.x + a2.x + a3.x) * li);
        float vy = rnaf((a0.y + a1.y + a2.y + a3.y) * li);
        int n = qt * 64 + row;
        *reinterpret_cast<float2*>(g_ao + ((size_t)bb * 2048 + n) * 512 + h * 64 + c2) =
            make_float2(vx, vy);
    }
}

// ===========================================================================
extern "C" void kernel_launch(void* const* d_in, const int* in_sizes, int n_in,
                              void* d_out, int out_size)
{
    const float* x     = (const float*)d_in[0];
    const float* wqkv  = (const float*)d_in[1];
    const float* wproj = (const float*)d_in[2];
    const float* bproj = (const float*)d_in[3];
    float* out = (float*)d_out;

    cudaFuncSetAttribute(attn_mma_kernel,
                         cudaFuncAttributeMaxDynamicSharedMemorySize, AT_BYTES);
    cudaFuncSetAttribute(qkv_mma_kernel,
                         cudaFuncAttributeMaxDynamicSharedMemorySize, G_SMEM_BYTES);
    cudaFuncSetAttribute(proj_mma_kernel,
                         cudaFuncAttributeMaxDynamicSharedMemorySize, G_SMEM_BYTES);

    round_x_kernel  <<<4096, 256>>>(x);
    transpose_kernel<<<dim3(48, 16), dim3(32, 8)>>>(wqkv,  0, 512, 1536);
    transpose_kernel<<<dim3(16, 16), dim3(32, 8)>>>(wproj, 1, 512, 512);

    qkv_mma_kernel <<<dim3(12, 64), 256, G_SMEM_BYTES>>>(out);
    attn_mma_kernel<<<dim3(32, 8, 4), 256, AT_BYTES>>>();
    proj_mma_kernel<<<dim3(4, 64), 256, G_SMEM_BYTES>>>(bproj, out);
}

// round 17
// speedup vs baseline: 2.0144x; 1.4294x over previous
#include <cuda_runtime.h>
#include <cuda_fp16.h>
#include <cstdint>

#define BB_  4
#define NN_  2048
#define CC_  512
#define HH_  8
#define HD_  64
// q pre-scale: (1/sqrt(64)) * log2(e)  -> scores arrive in log2 domain
#define QSCALE_ 0.18033688011112042f

// d_out layout: [ out (B*N*C) | k (B*H*N*hd) | v (B*H*N*hd) ]
#define KOFF_ (4u * 2048u * 512u)
#define VOFF_ (8u * 2048u * 512u)

// scratch
__device__ __half g_qh [BB_ * HH_ * NN_ * HD_];  // pre-scaled q, fp16
__device__ __half g_krh[BB_ * HH_ * NN_ * HD_];  // k, fp16
__device__ __half g_vth[BB_ * HH_ * HD_ * NN_];  // v, fp16, TRANSPOSED [b,h,d,n]
__device__ float g_ao [BB_ * NN_ * CC_];         // attention out, tf32-rounded
__device__ float g_xr [BB_ * NN_ * CC_];         // X, tf32-rounded
__device__ float g_wt [1536 * 512];              // W_qkv^T  [N][K], tf32-rounded
__device__ float g_wtp[512 * 512];               // W_proj^T [N][K], tf32-rounded

// ===========================================================================
// mma wrappers (base ISA, plain sm_103 target)
// ===========================================================================
__device__ __forceinline__ void mma_tf32(float (&d)[4], const uint32_t (&a)[4],
                                         const uint32_t (&b)[2]) {
    asm volatile(
        "mma.sync.aligned.m16n8k8.row.col.f32.tf32.tf32.f32 "
        "{%0,%1,%2,%3}, {%4,%5,%6,%7}, {%8,%9}, {%0,%1,%2,%3};"
        : "+f"(d[0]), "+f"(d[1]), "+f"(d[2]), "+f"(d[3])
        : "r"(a[0]), "r"(a[1]), "r"(a[2]), "r"(a[3]), "r"(b[0]), "r"(b[1]));
}
__device__ __forceinline__ void mma_f16(float (&d)[4], const uint32_t (&a)[4],
                                        const uint32_t (&b)[2]) {
    asm volatile(
        "mma.sync.aligned.m16n8k16.row.col.f32.f16.f16.f32 "
        "{%0,%1,%2,%3}, {%4,%5,%6,%7}, {%8,%9}, {%0,%1,%2,%3};"
        : "+f"(d[0]), "+f"(d[1]), "+f"(d[2]), "+f"(d[3])
        : "r"(a[0]), "r"(a[1]), "r"(a[2]), "r"(a[3]), "r"(b[0]), "r"(b[1]));
}

__device__ __forceinline__ uint32_t tf32_rna(float x) {
    uint32_t r;
    asm("cvt.rna.tf32.f32 %0, %1;" : "=r"(r) : "f"(x));
    return r;
}
__device__ __forceinline__ float rnaf(float x) {
    return __uint_as_float(tf32_rna(x));
}
__device__ __forceinline__ float4 rna4(float4 v) {
    v.x = rnaf(v.x); v.y = rnaf(v.y); v.z = rnaf(v.z); v.w = rnaf(v.w);
    return v;
}
__device__ __forceinline__ uint32_t smem_u32(const void* p) {
    uint32_t a;
    asm("{ .reg .u64 t; cvta.to.shared.u64 t, %1; cvt.u32.u64 %0, t; }"
        : "=r"(a) : "l"(p));
    return a;
}
__device__ __forceinline__ uint32_t h2pack(float lo, float hi) {
    __half2 h = __floats2half2_rn(lo, hi);
    return *reinterpret_cast<uint32_t*>(&h);
}

#define CP_ASYNC16(saddr, gptr) \
    asm volatile("cp.async.ca.shared.global [%0], [%1], 16;" \
        :: "r"(saddr), "l"(gptr) : "memory")
#define CP_COMMIT() \
    asm volatile("cp.async.commit_group;" ::: "memory")
#define CP_WAIT0() \
    asm volatile("cp.async.wait_group 0;" ::: "memory")

// fast 2^t on fma/alu pipes only (no MUFU). t >= -100 clamped; |err| ~ 3e-6.
__device__ __forceinline__ float fexp2(float t) {
    t = fmaxf(t, -100.f);
    float z = t + 12582912.f;
    int   n = __float_as_int(z) - 0x4B400000;
    float f = t - (z - 12582912.f);
    float p =        1.3333558e-3f;
    p = fmaf(p, f, 9.6181291e-3f);
    p = fmaf(p, f, 5.5504109e-2f);
    p = fmaf(p, f, 2.4022651e-1f);
    p = fmaf(p, f, 6.9314718e-1f);
    p = fmaf(p, f, 1.0f);
    return __int_as_float(__float_as_int(p) + (n << 23));
}

// ===========================================================================
// round_x: g_xr = tf32_rna(X)
// ===========================================================================
__global__ void round_x_kernel(const float* __restrict__ X)
{
    int i = blockIdx.x * blockDim.x + threadIdx.x;
    float4 v = reinterpret_cast<const float4*>(X)[i];
    reinterpret_cast<float4*>(g_xr)[i] = rna4(v);
}

// ===========================================================================
// W transpose + tf32 pre-round (dst resolved in device code)
// ===========================================================================
__global__ void transpose_kernel(const float* __restrict__ src,
                                 int which, int R, int C)
{
    float* dst = which ? g_wtp : g_wt;
    __shared__ float tile[32][33];
    int bx = blockIdx.x * 32, by = blockIdx.y * 32;
#pragma unroll
    for (int i = 0; i < 32; i += 8)
        tile[threadIdx.y + i][threadIdx.x] =
            src[(size_t)(by + threadIdx.y + i) * C + bx + threadIdx.x];
    __syncthreads();
#pragma unroll
    for (int i = 0; i < 32; i += 8)
        dst[(size_t)(bx + threadIdx.y + i) * R + by + threadIdx.x] =
            rnaf(tile[threadIdx.x][threadIdx.y + i]);
}

// ===========================================================================
// tf32x1 mma GEMM, cp.async double-buffered (verified R14 — byte-identical)
// ===========================================================================
#define GK_STR 36
#define G_BUF  (128 * GK_STR)
#define G_SMEM_BYTES (4 * G_BUF * 4)           /* 73728 */

#define G_ISSUE_STAGE(kofs, bufb)                                               \
    do {                                                                        \
        _Pragma("unroll")                                                       \
        for (int i = 0; i < 4; i++) {                                           \
            int idx = i * 256 + t;                                              \
            int row = idx >> 3, c4 = (idx & 7) * 4;                             \
            CP_ASYNC16(sbase + (uint32_t)((bufb) * G_BUF + row * GK_STR + c4) * 4u, \
                       Abase + (size_t)row * 512 + (kofs) + c4);                \
            CP_ASYNC16(sbase + (uint32_t)(2 * G_BUF + (bufb) * G_BUF + row * GK_STR + c4) * 4u, \
                       Bbase + (size_t)row * 512 + (kofs) + c4);                \
        }                                                                       \
        CP_COMMIT();                                                            \
    } while (0)

#define MMA_GEMM_BODY(APTR, BTPTR)                                              \
    extern __shared__ float gsm[];                                              \
    const int t    = threadIdx.x;                                               \
    const int warp = t >> 5, lane = t & 31;                                     \
    const int wm   = warp >> 2, wn = warp & 3;                                  \
    const int lg   = lane >> 2, lq = lane & 3;                                  \
    const int row0 = blockIdx.y * 128, col0 = blockIdx.x * 128;                 \
    const float* Abase = (APTR) + (size_t)row0 * 512;                           \
    const float* Bbase = (BTPTR) + (size_t)col0 * 512;                          \
    const uint32_t sbase = smem_u32(gsm);                                       \
    float acc[4][4][4];                                                         \
    _Pragma("unroll") for (int i = 0; i < 4; i++)                               \
        _Pragma("unroll") for (int j = 0; j < 4; j++)                           \
            _Pragma("unroll") for (int c = 0; c < 4; c++) acc[i][j][c] = 0.f;   \
    G_ISSUE_STAGE(0, 0);                                                        \
    int buf = 0;                                                                \
    for (int st = 0; st < 16; st++) {                                           \
        CP_WAIT0();                                                             \
        __syncthreads();                                                        \
        if (st < 15) G_ISSUE_STAGE((st + 1) * 32, buf ^ 1);                     \
        const float* sA = gsm + buf * G_BUF;                                    \
        const float* sB = gsm + 2 * G_BUF + buf * G_BUF;                        \
        _Pragma("unroll")                                                       \
        for (int ks = 0; ks < 4; ks++) {                                        \
            const int k0 = ks * 8;                                              \
            uint32_t a[4][4], b[4][2];                                          \
            _Pragma("unroll")                                                   \
            for (int mf = 0; mf < 4; mf++) {                                    \
                int rA = wm * 64 + mf * 16 + lg;                                \
                a[mf][0] = __float_as_uint(sA[rA * GK_STR + k0 + lq]);          \
                a[mf][1] = __float_as_uint(sA[(rA + 8) * GK_STR + k0 + lq]);    \
                a[mf][2] = __float_as_uint(sA[rA * GK_STR + k0 + lq + 4]);      \
                a[mf][3] = __float_as_uint(sA[(rA + 8) * GK_STR + k0 + lq + 4]);\
            }                                                                   \
            _Pragma("unroll")                                                   \
            for (int nf = 0; nf < 4; nf++) {                                    \
                int nb = wn * 32 + nf * 8 + lg;                                 \
                b[nf][0] = __float_as_uint(sB[nb * GK_STR + k0 + lq]);          \
                b[nf][1] = __float_as_uint(sB[nb * GK_STR + k0 + lq + 4]);      \
            }                                                                   \
            _Pragma("unroll")                                                   \
            for (int mf = 0; mf < 4; mf++)                                      \
                _Pragma("unroll")                                               \
                for (int nf = 0; nf < 4; nf++)                                  \
                    mma_tf32(acc[mf][nf], a[mf], b[nf]);                        \
        }                                                                       \
        buf ^= 1;                                                               \
    }

// ---------------------------------------------------------------------------
// QKV GEMM (tf32x1): q -> g_qh (scaled, fp16), k -> d_out + g_krh,
// v -> d_out + g_vth (transposed fp16).
// ---------------------------------------------------------------------------
__global__ __launch_bounds__(256, 2) void qkv_mma_kernel(float* __restrict__ dout)
{
    MMA_GEMM_BODY(g_xr, g_wt)

    const int s = col0 >> 9;                       // 0=q,1=k,2=v (block-uniform)
    const int h = ((col0 + wn * 32) >> 6) & 7;     // warp-uniform
#pragma unroll
    for (int mf = 0; mf < 4; mf++) {
        int m  = row0 + wm * 64 + mf * 16 + lg;
        int bb = m >> 11, n = m & 2047;
#pragma unroll
        for (int nf = 0; nf < 4; nf++) {
            int d = ((col0 + wn * 32 + nf * 8) & 63) + 2 * lq;
            size_t base0 = (((size_t)(bb * 8 + h)) * 2048 + n) * 64 + d;
            size_t base1 = base0 + 8 * 64;
            float2 v0 = make_float2(acc[mf][nf][0], acc[mf][nf][1]);
            float2 v1 = make_float2(acc[mf][nf][2], acc[mf][nf][3]);
            if (s == 0) {
                *reinterpret_cast<uint32_t*>(&g_qh[base0]) =
                    h2pack(v0.x * QSCALE_, v0.y * QSCALE_);
                *reinterpret_cast<uint32_t*>(&g_qh[base1]) =
                    h2pack(v1.x * QSCALE_, v1.y * QSCALE_);
            } else if (s == 1) {
                *reinterpret_cast<float2*>(dout + KOFF_ + base0) = v0;
                *reinterpret_cast<float2*>(dout + KOFF_ + base1) = v1;
                *reinterpret_cast<uint32_t*>(&g_krh[base0]) = h2pack(v0.x, v0.y);
                *reinterpret_cast<uint32_t*>(&g_krh[base1]) = h2pack(v1.x, v1.y);
            } else {
                *reinterpret_cast<float2*>(dout + VOFF_ + base0) = v0;
                *reinterpret_cast<float2*>(dout + VOFF_ + base1) = v1;
                size_t vt = ((size_t)(bb * 8 + h) * 64 + d) * 2048 + n;
                g_vth[vt]        = __float2half_rn(v0.x);
                g_vth[vt + 2048] = __float2half_rn(v0.y);
                g_vth[vt + 8]        = __float2half_rn(v1.x);
                g_vth[vt + 2048 + 8] = __float2half_rn(v1.y);
            }
        }
    }
}

// ---------------------------------------------------------------------------
// Proj GEMM (tf32x1): g_ao (pre-rounded) @ W_proj + bias -> d_out[0..]
// ---------------------------------------------------------------------------
__global__ __launch_bounds__(256, 2) void proj_mma_kernel(
    const float* __restrict__ bias, float* __restrict__ dout)
{
    MMA_GEMM_BODY(g_ao, g_wtp)

#pragma unroll
    for (int mf = 0; mf < 4; mf++) {
        int m = row0 + wm * 64 + mf * 16 + lg;
#pragma unroll
        for (int nf = 0; nf < 4; nf++) {
            int gcol = col0 + wn * 32 + nf * 8 + 2 * lq;
            float bx = bias[gcol], by = bias[gcol + 1];
            float* d0 = dout + (size_t)m * 512 + gcol;
            float* d1 = dout + (size_t)(m + 8) * 512 + gcol;
            *reinterpret_cast<float2*>(d0) =
                make_float2(acc[mf][nf][0] + bx, acc[mf][nf][1] + by);
            *reinterpret_cast<float2*>(d1) =
                make_float2(acc[mf][nf][2] + bx, acc[mf][nf][3] + by);
        }
    }
}

// ===========================================================================
// Flash attention on fp16 mma (m16n8k16, fp32 accumulate). Same precision as
// the tf32 path (11-bit mantissa), half the mma count and fragment LDS, and
// ZERO shfl: the S-accumulator layout packs directly into PV A-fragments.
// Register-P (R15/R16 core), cp.async pipelined K / V(transposed).
// SMEM (halves): sQ[64][72], sK[128][72], sVT[64][136]; 45056 B tiles;
// partial-O reduction reuses floats [0,16384); sRed/sLinv above at 65536 B.
// Dynamic smem 66816 B -> 2 CTAs/SM.
// ===========================================================================
#define SQH_STR 72
#define SKH_STR 72
#define SVT_STR 136
#define OFF_Q   0
#define OFF_K   9216
#define OFF_VT  27648
#define AT_BYTES (65536 + 1024 + 256)

__global__ __launch_bounds__(256, 2) void attn_mma_kernel()
{
    extern __shared__ float sm[];
    __half* sQh  = reinterpret_cast<__half*>(reinterpret_cast<char*>(sm) + OFF_Q);
    __half* sKh  = reinterpret_cast<__half*>(reinterpret_cast<char*>(sm) + OFF_K);
    __half* sVTh = reinterpret_cast<__half*>(reinterpret_cast<char*>(sm) + OFF_VT);
    float* sRed  = sm + 16384;                     // [256]
    float* sLinv = sm + 16384 + 256;               // [64]
    const uint32_t sbase = smem_u32(sm);

    const int t    = threadIdx.x;
    const int warp = t >> 5, lane = t & 31;
    const int wm   = warp >> 2, wn = warp & 3;
    const int lg   = lane >> 2, lq = lane & 3;
    const int qt   = blockIdx.x, h = blockIdx.y, bb = blockIdx.z;

    const size_t bh = (size_t)(bb * 8 + h);
    const __half* qb  = g_qh  + (bh * 2048 + (size_t)qt * 64) * 64;
    const __half* kb  = g_krh + bh * 2048 * 64;
    const __half* vtb = g_vth + bh * 64 * 2048;

    // preload K(0): 128 rows x 128B
#pragma unroll
    for (int i = 0; i < 4; i++) {
        int idx = i * 256 + t;
        int row = idx >> 3, c = idx & 7;
        CP_ASYNC16(sbase + OFF_K + (uint32_t)(row * 144 + c * 16),
                   kb + (size_t)row * 64 + c * 8);
    }
    CP_COMMIT();

    // load Q tile [64][64] halves
#pragma unroll
    for (int i = t; i < 512; i += 256) {
        int row = i >> 3, c = i & 7;
        uint4 v = *reinterpret_cast<const uint4*>(qb + row * 64 + c * 8);
        *reinterpret_cast<uint4*>(reinterpret_cast<char*>(sm) + OFF_Q + row * 144 + c * 16) = v;
    }

    float o[2][8][4];
    float lsum[2][2];
#pragma unroll
    for (int mi = 0; mi < 2; mi++) {
        lsum[mi][0] = 0.f; lsum[mi][1] = 0.f;
#pragma unroll
        for (int nd = 0; nd < 8; nd++)
#pragma unroll
            for (int c = 0; c < 4; c++) o[mi][nd][c] = 0.f;
    }

    float s[2][4][4];

    for (int j = 0; j < 16; j++) {
        const int j0 = j * 128;

        // ---- K(j) ready; prev PV done with sVT ----
        CP_WAIT0();
        __syncthreads();
        // V^T(j) copies during QK(j): 64 d-rows x 256B
#pragma unroll
        for (int i = 0; i < 4; i++) {
            int idx = i * 256 + t;
            int row = idx >> 4, c = idx & 15;
            CP_ASYNC16(sbase + OFF_VT + (uint32_t)(row * 272 + c * 16),
                       vtb + (size_t)row * 2048 + j0 + c * 8);
        }
        CP_COMMIT();

        // ---- S = Q K^T (fp16 mma, k16) ----
#pragma unroll
        for (int mi = 0; mi < 2; mi++)
#pragma unroll
            for (int ni = 0; ni < 4; ni++)
#pragma unroll
                for (int c = 0; c < 4; c++) s[mi][ni][c] = 0.f;

#pragma unroll
        for (int ks = 0; ks < 4; ks++) {
            const int k0 = ks * 16;
            uint32_t a[2][4], b[4][2];
#pragma unroll
            for (int mi = 0; mi < 2; mi++) {
                int rA = wm * 32 + mi * 16 + lg;
                a[mi][0] = *reinterpret_cast<const uint32_t*>(&sQh[rA * SQH_STR + k0 + 2 * lq]);
                a[mi][1] = *reinterpret_cast<const uint32_t*>(&sQh[(rA + 8) * SQH_STR + k0 + 2 * lq]);
                a[mi][2] = *reinterpret_cast<const uint32_t*>(&sQh[rA * SQH_STR + k0 + 2 * lq + 8]);
                a[mi][3] = *reinterpret_cast<const uint32_t*>(&sQh[(rA + 8) * SQH_STR + k0 + 2 * lq + 8]);
            }
#pragma unroll
            for (int ni = 0; ni < 4; ni++) {
                int nb = wn * 32 + ni * 8 + lg;
                b[ni][0] = *reinterpret_cast<const uint32_t*>(&sKh[nb * SKH_STR + k0 + 2 * lq]);
                b[ni][1] = *reinterpret_cast<const uint32_t*>(&sKh[nb * SKH_STR + k0 + 2 * lq + 8]);
            }
#pragma unroll
            for (int mi = 0; mi < 2; mi++)
#pragma unroll
                for (int ni = 0; ni < 4; ni++)
                    mma_f16(s[mi][ni], a[mi], b[ni]);
        }

        // ---- P = 2^S in registers; lsum from fp32 P ----
#pragma unroll
        for (int mi = 0; mi < 2; mi++)
#pragma unroll
            for (int ni = 0; ni < 4; ni++) {
                float p0 = fexp2(s[mi][ni][0]);
                float p1 = fexp2(s[mi][ni][1]);
                float p2 = fexp2(s[mi][ni][2]);
                float p3 = fexp2(s[mi][ni][3]);
                lsum[mi][0] += p0 + p1;
                lsum[mi][1] += p2 + p3;
                s[mi][ni][0] = p0; s[mi][ni][1] = p1;
                s[mi][ni][2] = p2; s[mi][ni][3] = p3;
            }

        // ---- V^T(j) ready; QK done with sK ----
        CP_WAIT0();
        __syncthreads();
        if (j < 15) {
#pragma unroll
            for (int i = 0; i < 4; i++) {
                int idx = i * 256 + t;
                int row = idx >> 3, c = idx & 7;
                CP_ASYNC16(sbase + OFF_K + (uint32_t)(row * 144 + c * 16),
                           kb + (size_t)(j0 + 128 + row) * 64 + c * 8);
            }
            CP_COMMIT();
        }

        // ---- O += P V over this warp's j-chunk (2 x k16), fp16 mma ----
#pragma unroll
        for (int tt = 0; tt < 2; tt++) {
            uint32_t aP[2][4];
#pragma unroll
            for (int mi = 0; mi < 2; mi++) {
                aP[mi][0] = h2pack(s[mi][2 * tt][0],     s[mi][2 * tt][1]);
                aP[mi][1] = h2pack(s[mi][2 * tt][2],     s[mi][2 * tt][3]);
                aP[mi][2] = h2pack(s[mi][2 * tt + 1][0], s[mi][2 * tt + 1][1]);
                aP[mi][3] = h2pack(s[mi][2 * tt + 1][2], s[mi][2 * tt + 1][3]);
            }
            const int jb = wn * 32 + tt * 16;
#pragma unroll
            for (int nd = 0; nd < 8; nd++) {
                uint32_t b[2];
                b[0] = *reinterpret_cast<const uint32_t*>(
                    &sVTh[(nd * 8 + lg) * SVT_STR + jb + 2 * lq]);
                b[1] = *reinterpret_cast<const uint32_t*>(
                    &sVTh[(nd * 8 + lg) * SVT_STR + jb + 2 * lq + 8]);
                mma_f16(o[0][nd], aP[0], b);
                mma_f16(o[1][nd], aP[1], b);
            }
        }
    }

    // ---- lsum reduction across quads ----
#pragma unroll
    for (int mi = 0; mi < 2; mi++)
#pragma unroll
        for (int hf = 0; hf < 2; hf++) {
            float v = lsum[mi][hf];
            v += __shfl_xor_sync(0xffffffffu, v, 1);
            v += __shfl_xor_sync(0xffffffffu, v, 2);
            lsum[mi][hf] = v;
        }

    __syncthreads();                 // all PV reads of sVT complete

    // ---- store partial O to SMEM [wn][64][64] floats (reuses tile region) ----
#pragma unroll
    for (int mi = 0; mi < 2; mi++) {
        int row = wm * 32 + mi * 16 + lg;
        int base = wn * 4096 + row * 64 + 2 * lq;
#pragma unroll
        for (int nd = 0; nd < 8; nd++) {
            *reinterpret_cast<float2*>(&sm[base + nd * 8]) =
                make_float2(o[mi][nd][0], o[mi][nd][1]);
            *reinterpret_cast<float2*>(&sm[base + 512 + nd * 8]) =
                make_float2(o[mi][nd][2], o[mi][nd][3]);
        }
    }
    if (lq == 0) {
#pragma unroll
        for (int mi = 0; mi < 2; mi++) {
            sRed[wn * 64 + wm * 32 + mi * 16 + lg]     = lsum[mi][0];
            sRed[wn * 64 + wm * 32 + mi * 16 + lg + 8] = lsum[mi][1];
        }
    }
    __syncthreads();

    if (t < 64)
        sLinv[t] = __fdividef(1.f, sRed[t] + sRed[64 + t] + sRed[128 + t] + sRed[192 + t]);
    __syncthreads();

    // ---- reduce 4 partials, normalize, round, write g_ao ----
    for (int i2 = t; i2 < 2048; i2 += 256) {
        int row = i2 >> 5, c2 = (i2 & 31) * 2;
        float2 a0 = *reinterpret_cast<float2*>(&sm[0 * 4096 + row * 64 + c2]);
        float2 a1 = *reinterpret_cast<float2*>(&sm[1 * 4096 + row * 64 + c2]);
        float2 a2 = *reinterpret_cast<float2*>(&sm[2 * 4096 + row * 64 + c2]);
        float2 a3 = *reinterpret_cast<float2*>(&sm[3 * 4096 + row * 64 + c2]);
        float li = sLinv[row];
        float vx = rnaf((a0.x + a1.x + a2.x + a3.x) * li);
        float vy = rnaf((a0.y + a1.y + a2.y + a3.y) * li);
        int n = qt * 64 + row;
        *reinterpret_cast<float2*>(g_ao + ((size_t)bb * 2048 + n) * 512 + h * 64 + c2) =
            make_float2(vx, vy);
    }
}

// ===========================================================================
extern "C" void kernel_launch(void* const* d_in, const int* in_sizes, int n_in,
                              void* d_out, int out_size)
{
    const float* x     = (const float*)d_in[0];
    const float* wqkv  = (const float*)d_in[1];
    const float* wproj = (const float*)d_in[2];
    const float* bproj = (const float*)d_in[3];
    float* out = (float*)d_out;

    cudaFuncSetAttribute(attn_mma_kernel,
                         cudaFuncAttributeMaxDynamicSharedMemorySize, AT_BYTES);
    cudaFuncSetAttribute(qkv_mma_kernel,
                         cudaFuncAttributeMaxDynamicSharedMemorySize, G_SMEM_BYTES);
    cudaFuncSetAttribute(proj_mma_kernel,
                         cudaFuncAttributeMaxDynamicSharedMemorySize, G_SMEM_BYTES);

    round_x_kernel  <<<4096, 256>>>(x);
    transpose_kernel<<<dim3(48, 16), dim3(32, 8)>>>(wqkv,  0, 512, 1536);
    transpose_kernel<<<dim3(16, 16), dim3(32, 8)>>>(wproj, 1, 512, 512);

    qkv_mma_kernel <<<dim3(12, 64), 256, G_SMEM_BYTES>>>(out);
    attn_mma_kernel<<<dim3(32, 8, 4), 256, AT_BYTES>>>();
    proj_mma_kernel<<<dim3(4, 64), 256, G_SMEM_BYTES>>>(bproj, out);
}